// round 10
// baseline (speedup 1.0000x reference)
#include <cuda_runtime.h>
#include <cstdint>

#define BB   16
#define NSS  128
#define TT   64
#define DD   512
#define HH   512
#define NB_LSTM 128

// ---------------- scratch (device globals) ----------------
__device__ float g_attn_feat[BB * NSS * HH];
__device__ float g_hop_feat [BB * NSS * HH];
__device__ float g_xcat     [TT * BB * DD];      // row = t*16+b
__device__ float g_X        [TT * BB * 4 * HH];  // gate preacts
__device__ float g_qa       [BB * TT * HH];      // row = b*64+t
__device__ float g_qb       [BB * TT * HH];
__device__ float g_hbuf     [2][BB * HH];
__device__ unsigned g_cnt8  [TT][512];           // 8 counters/step @256B stride (idx (cta&7)*64)

// ---------------- helpers ----------------
__device__ __forceinline__ float fast_tanh(float x) {
    float e, r;
    asm("ex2.approx.f32 %0, %1;" : "=f"(e) : "f"(x * 2.885390081777927f));
    asm("rcp.approx.f32 %0, %1;" : "=f"(r) : "f"(e + 1.0f));
    return fmaf(-2.0f, r, 1.0f);
}
__device__ __forceinline__ float sigm(float x) { return 1.0f / (1.0f + __expf(-x)); }

__device__ __forceinline__ unsigned long long ffma2(
    unsigned long long a, unsigned long long b, unsigned long long c) {
    unsigned long long d;
    asm("fma.rn.f32x2 %0, %1, %2, %3;" : "=l"(d) : "l"(a), "l"(b), "l"(c));
    return d;
}
__device__ __forceinline__ float pairsum(unsigned long long v) {
    float lo, hi;
    asm("mov.b64 {%0, %1}, %2;" : "=f"(lo), "=f"(hi) : "l"(v));
    return lo + hi;
}
__device__ __forceinline__ void atom_add_release(unsigned* p) {
    unsigned old;
    asm volatile("atom.release.gpu.global.add.u32 %0, [%1], 1;"
                 : "=r"(old) : "l"(p) : "memory");
}
__device__ __forceinline__ unsigned ld_acquire(const unsigned* p) {
    unsigned v;
    asm volatile("ld.acquire.gpu.global.u32 %0, [%1];" : "=r"(v) : "l"(p) : "memory");
    return v;
}

// ============ BIG SGEMM: 128x128 tile, BK=8, 256 threads, 8x8 micro ============
#define SBS 132
template<bool TRANSB, bool BIAS>
__global__ void __launch_bounds__(256) sgemm_big(
    const float* __restrict__ A,
    const float* __restrict__ B0, const float* __restrict__ B1,
    const float* __restrict__ bi1, const float* __restrict__ bi2,
    float* __restrict__ C0, float* __restrict__ C1,
    int M, int N, int K)
{
    const float* __restrict__ Bm = blockIdx.z ? B1 : B0;
    float* __restrict__ C = blockIdx.z ? C1 : C0;

    __shared__ float As[2][8 * SBS];
    __shared__ float Bs[2][8 * SBS];

    const int tid = threadIdx.x;
    const int m0 = blockIdx.y * 128, n0 = blockIdx.x * 128;
    const int row0 = (tid >> 4) << 3;
    const int col0 = (tid & 15) << 3;

    const int am = tid >> 1, akq = (tid & 1) << 2;
    const float* Ap = A + (size_t)(m0 + am) * K + akq;
    int bn = 0, bkq = 0, bkr = 0, bn4 = 0;
    const float* Bp;
    if (TRANSB) { bn = tid >> 1; bkq = (tid & 1) << 2; Bp = Bm + (size_t)(n0 + bn) * K + bkq; }
    else        { bkr = tid >> 5; bn4 = (tid & 31) << 2; Bp = Bm + (size_t)bkr * N + n0 + bn4; }

    float acc[8][8] = {};
    float4 av, bv;

    av = *(const float4*)(Ap);
    bv = *(const float4*)(Bp);
    {
        float* as = As[0];
        as[(akq+0)*SBS + am] = av.x; as[(akq+1)*SBS + am] = av.y;
        as[(akq+2)*SBS + am] = av.z; as[(akq+3)*SBS + am] = av.w;
        float* bs = Bs[0];
        if (TRANSB) {
            bs[(bkq+0)*SBS + bn] = bv.x; bs[(bkq+1)*SBS + bn] = bv.y;
            bs[(bkq+2)*SBS + bn] = bv.z; bs[(bkq+3)*SBS + bn] = bv.w;
        } else {
            *(float4*)(bs + bkr*SBS + bn4) = bv;
        }
    }
    __syncthreads();

    int buf = 0;
    for (int k0 = 8; k0 <= K; k0 += 8) {
        const bool more = (k0 < K);
        if (more) {
            av = *(const float4*)(Ap + k0);
            if (TRANSB) bv = *(const float4*)(Bp + k0);
            else        bv = *(const float4*)(Bm + (size_t)(k0 + bkr) * N + n0 + bn4);
        }
        const float* as = As[buf];
        const float* bs = Bs[buf];
#pragma unroll
        for (int kk = 0; kk < 8; kk++) {
            float4 a0 = *(const float4*)(as + kk*SBS + row0);
            float4 a1 = *(const float4*)(as + kk*SBS + row0 + 4);
            float4 c0 = *(const float4*)(bs + kk*SBS + col0);
            float4 c1 = *(const float4*)(bs + kk*SBS + col0 + 4);
            float aa[8] = {a0.x,a0.y,a0.z,a0.w,a1.x,a1.y,a1.z,a1.w};
            float bb[8] = {c0.x,c0.y,c0.z,c0.w,c1.x,c1.y,c1.z,c1.w};
#pragma unroll
            for (int i = 0; i < 8; i++)
#pragma unroll
                for (int j = 0; j < 8; j++) acc[i][j] = fmaf(aa[i], bb[j], acc[i][j]);
        }
        if (more) {
            float* asn = As[buf ^ 1];
            asn[(akq+0)*SBS + am] = av.x; asn[(akq+1)*SBS + am] = av.y;
            asn[(akq+2)*SBS + am] = av.z; asn[(akq+3)*SBS + am] = av.w;
            float* bsn = Bs[buf ^ 1];
            if (TRANSB) {
                bsn[(bkq+0)*SBS + bn] = bv.x; bsn[(bkq+1)*SBS + bn] = bv.y;
                bsn[(bkq+2)*SBS + bn] = bv.z; bsn[(bkq+3)*SBS + bn] = bv.w;
            } else {
                *(float4*)(bsn + bkr*SBS + bn4) = bv;
            }
        }
        __syncthreads();
        buf ^= 1;
    }

    float bias[8] = {};
    if (BIAS) {
#pragma unroll
        for (int j = 0; j < 8; j++) bias[j] = bi1[n0+col0+j] + bi2[n0+col0+j];
    }
#pragma unroll
    for (int i = 0; i < 8; i++) {
        float4 o0 = {acc[i][0]+bias[0], acc[i][1]+bias[1], acc[i][2]+bias[2], acc[i][3]+bias[3]};
        float4 o1 = {acc[i][4]+bias[4], acc[i][5]+bias[5], acc[i][6]+bias[6], acc[i][7]+bias[7]};
        float* cp = C + (size_t)(m0 + row0 + i) * N + n0 + col0;
        *(float4*)(cp)     = o0;
        *(float4*)(cp + 4) = o1;
    }
}

// ---------------- prep: xcat + maxpool + h0 + counter reset ----------------
__global__ void prep_kernel(const float* __restrict__ attn_mem,
                            const float* __restrict__ lstm_in,
                            const float* __restrict__ init_h,
                            const int* __restrict__ msz)
{
    const int t = blockIdx.x, b = blockIdx.y, d = threadIdx.x;
    if (b == 0) g_cnt8[t][d] = 0u;     // stream-ordered before lstm_kernel
    if (t == 0) {
        const int ms = msz[b];
        float m = -3.0e38f;
        for (int n = 0; n < ms; n++)
            m = fmaxf(m, attn_mem[((size_t)b * NSS + n) * DD + d]);
        g_xcat[(size_t)b * DD + d] = m;
        g_hbuf[0][b * HH + d] = init_h[d];
    } else {
        g_xcat[((size_t)t * BB + b) * DD + d] =
            lstm_in[((size_t)b * (TT - 1) + (t - 1)) * DD + d];
    }
}

// ---------------- persistent LSTM: 128 CTAs, 8-way split release/acquire barrier ----------------
__global__ void __launch_bounds__(256) lstm_kernel(const float* __restrict__ Whh,
                                                   const float* __restrict__ init_c)
{
    __shared__ float h_sm[16][516];        // 33 KB; aliased as red after compute
    __shared__ float gsm[16][16];
    __shared__ float c_sm[16][4];

    float* red = &h_sm[0][0];              // [16 kc][260] scratch (aliased)

    const int tid = threadIdx.x;
    const int cta = blockIdx.x;
    const int hd0 = cta * 4;
    const int kc = tid & 15;
    const int rr = (tid >> 4) & 3;
    const int bq = tid >> 6;

    const float* wp0 = Whh + ((size_t)(0*HH + hd0 + rr)) * HH + kc * 4;
    const float* wp1 = Whh + ((size_t)(1*HH + hd0 + rr)) * HH + kc * 4;
    const float* wp2 = Whh + ((size_t)(2*HH + hd0 + rr)) * HH + kc * 4;
    const float* wp3 = Whh + ((size_t)(3*HH + hd0 + rr)) * HH + kc * 4;

    if (tid < 64) { int b = tid >> 2, l = tid & 3; c_sm[b][l] = init_c[hd0 + l]; }

    const int rowX = tid >> 4;
    const int bX   = tid & 15;

    for (int s = 0; s < TT; s++) {
        // prefetch this step's X preactivation (independent of h)
        float xv = __ldcg(&g_X[((size_t)s * BB + bX) * (4 * HH) + (rowX >> 2) * HH + hd0 + (rowX & 3)]);

        if (s > 0) {
            if (tid < 8) {
                while (ld_acquire(&g_cnt8[s - 1][tid * 64]) < 16u) { }
            }
        }
        __syncthreads();   // broadcasts the 8 acquire orderings CTA-wide

        // stage h into h_sm[b][k]
        const float4* hb = (const float4*)g_hbuf[s & 1];
#pragma unroll
        for (int i2 = 0; i2 < 8; i2++) {
            int i = tid + 256 * i2;
            float4 hv = __ldcg(hb + i);
            int b = i >> 7, k4 = (i & 127) << 2;
            *(float4*)(&h_sm[b][k4]) = hv;
        }
        __syncthreads();

        unsigned long long acc[4][4];
#pragma unroll
        for (int g = 0; g < 4; g++)
#pragma unroll
            for (int bi = 0; bi < 4; bi++) acc[g][bi] = 0ULL;

#pragma unroll
        for (int j = 0; j < 8; j++) {
            const ulonglong2 w0 = *(const ulonglong2*)(wp0 + j * 64);
            const ulonglong2 w1 = *(const ulonglong2*)(wp1 + j * 64);
            const ulonglong2 w2 = *(const ulonglong2*)(wp2 + j * 64);
            const ulonglong2 w3 = *(const ulonglong2*)(wp3 + j * 64);
#pragma unroll
            for (int bi = 0; bi < 4; bi++) {
                const ulonglong2 h2 = *(const ulonglong2*)(&h_sm[bq * 4 + bi][kc * 4 + j * 64]);
                acc[0][bi] = ffma2(w0.x, h2.x, acc[0][bi]);
                acc[0][bi] = ffma2(w0.y, h2.y, acc[0][bi]);
                acc[1][bi] = ffma2(w1.x, h2.x, acc[1][bi]);
                acc[1][bi] = ffma2(w1.y, h2.y, acc[1][bi]);
                acc[2][bi] = ffma2(w2.x, h2.x, acc[2][bi]);
                acc[2][bi] = ffma2(w2.y, h2.y, acc[2][bi]);
                acc[3][bi] = ffma2(w3.x, h2.x, acc[3][bi]);
                acc[3][bi] = ffma2(w3.y, h2.y, acc[3][bi]);
            }
        }
        __syncthreads();   // h_sm reads done before aliasing as red

#pragma unroll
        for (int g = 0; g < 4; g++)
#pragma unroll
            for (int bi = 0; bi < 4; bi++)
                red[kc * 260 + (g * 4 + rr) * 16 + (bq * 4 + bi)] = pairsum(acc[g][bi]);
        __syncthreads();

        {
            float sum = xv;
#pragma unroll
            for (int i = 0; i < 16; i++) sum += red[i * 260 + rowX * 16 + bX];
            gsm[rowX][bX] = sum;
        }
        __syncthreads();

        if (tid < 64) {
            int b = tid >> 2, l = tid & 3;
            float gi = gsm[0 + l][b], gf = gsm[4 + l][b];
            float gg = gsm[8 + l][b], go = gsm[12 + l][b];
            float c = sigm(gf) * c_sm[b][l] + sigm(gi) * fast_tanh(gg);
            float h = sigm(go) * fast_tanh(c);
            c_sm[b][l] = c;
            g_hbuf[(s + 1) & 1][b * HH + hd0 + l] = h;
            g_qa[((size_t)b * TT + s) * HH + hd0 + l] = h;
        }
        __syncthreads();   // h stores complete CTA-wide before the release below
        if (tid == 0 && s < TT - 1) {
            atom_add_release(&g_cnt8[s][(cta & 7) * 64]);   // release orders prior h writes
        }
    }
}

// ---------------- hop: fused q@Wq + score + softmax + weighted-sum; 8 t/block ----------------
__global__ void __launch_bounds__(256) hop_kernel(
    const float* __restrict__ qin, const float* __restrict__ wq,
    const float* __restrict__ feat, const float* __restrict__ v,
    const int* __restrict__ msz, float* __restrict__ qout)
{
    __shared__ float buf[8 * HH];           // 16 KB: qin during gemm, partials in phase 5
    __shared__ float qsm[8 * HH];           // 16 KB: qw = qin @ wq
    __shared__ float vsm[HH];               // 2 KB
    __shared__ float p[8][NSS];             // 4 KB

    const int tg = blockIdx.x, b = blockIdx.y, tid = threadIdx.x;
    const int t0 = tg * 8;

    // phase 1: load qin rows + v
    {
        const float4* qsrc = (const float4*)(qin + ((size_t)b * TT + t0) * HH);
        float4* qdst = (float4*)buf;
#pragma unroll
        for (int i = 0; i < 4; i++) qdst[tid + 256 * i] = qsrc[tid + 256 * i];
        vsm[tid] = v[tid]; vsm[tid + 256] = v[tid + 256];
    }
    __syncthreads();

    // phase 2: qw[t][h] = sum_k qin[t][k] * wq[k][h]; thread owns h = tid, tid+256
    {
        float acc0[8] = {}, acc1[8] = {};
        const float* wqp = wq + tid;
        for (int k = 0; k < HH; k += 2) {
            float w0a = wqp[(size_t)k * HH];
            float w1a = wqp[(size_t)k * HH + 256];
            float w0b = wqp[(size_t)(k + 1) * HH];
            float w1b = wqp[(size_t)(k + 1) * HH + 256];
#pragma unroll
            for (int t = 0; t < 8; t++) {
                float qa_ = buf[t * HH + k];
                float qb_ = buf[t * HH + k + 1];
                acc0[t] = fmaf(qa_, w0a, fmaf(qb_, w0b, acc0[t]));
                acc1[t] = fmaf(qa_, w1a, fmaf(qb_, w1b, acc1[t]));
            }
        }
#pragma unroll
        for (int t = 0; t < 8; t++) {
            qsm[t * HH + tid]       = acc0[t];
            qsm[t * HH + tid + 256] = acc1[t];
        }
    }
    __syncthreads();

    // phase 3: scores (warp wid <-> t = t0+wid)
    const int wid = tid >> 5, lane = tid & 31;
    const int ms = msz[b];
    const float* qt = qsm + wid * HH;
    for (int n = 0; n < NSS; n++) {
        const float* f = feat + ((size_t)b * NSS + n) * HH;
        float s = 0.f;
#pragma unroll 4
        for (int j = 0; j < 16; j++) {
            int k = lane + (j << 5);
            s += vsm[k] * fast_tanh(f[k] + qt[k]);
        }
#pragma unroll
        for (int o = 16; o; o >>= 1) s += __shfl_xor_sync(0xffffffffu, s, o);
        if (lane == 0) p[wid][n] = (n < ms) ? s : -1e30f;
    }
    __syncthreads();
    // phase 4: softmax per t
    {
        float x0 = p[wid][lane], x1 = p[wid][lane+32], x2 = p[wid][lane+64], x3 = p[wid][lane+96];
        float m = fmaxf(fmaxf(x0, x1), fmaxf(x2, x3));
#pragma unroll
        for (int o = 16; o; o >>= 1) m = fmaxf(m, __shfl_xor_sync(0xffffffffu, m, o));
        float e0 = __expf(x0 - m), e1 = __expf(x1 - m), e2 = __expf(x2 - m), e3 = __expf(x3 - m);
        float s = e0 + e1 + e2 + e3;
#pragma unroll
        for (int o = 16; o; o >>= 1) s += __shfl_xor_sync(0xffffffffu, s, o);
        float inv = 1.f / s;
        p[wid][lane] = e0*inv; p[wid][lane+32] = e1*inv; p[wid][lane+64] = e2*inv; p[wid][lane+96] = e3*inv;
    }
    __syncthreads();
    // phase 5: weighted sum (buf re-used as partial buffer)
    {
        float4* part4 = (float4*)buf;
        const int g = tid >> 7;
        const int hc = tid & 127;
        float4 acc[8] = {};
        const int nlo = g * 64;
#pragma unroll 2
        for (int n = nlo; n < nlo + 64; n++) {
            float4 fv = *(const float4*)(feat + ((size_t)b * NSS + n) * HH + hc * 4);
#pragma unroll
            for (int t = 0; t < 8; t++) {
                float pw = p[t][n];
                acc[t].x = fmaf(pw, fv.x, acc[t].x);
                acc[t].y = fmaf(pw, fv.y, acc[t].y);
                acc[t].z = fmaf(pw, fv.z, acc[t].z);
                acc[t].w = fmaf(pw, fv.w, acc[t].w);
            }
        }
        if (g == 1) {
#pragma unroll
            for (int t = 0; t < 8; t++) part4[t * 128 + hc] = acc[t];
        }
        __syncthreads();
        if (g == 0) {
#pragma unroll
            for (int t = 0; t < 8; t++) {
                float4 pv = part4[t * 128 + hc];
                float4 o = {acc[t].x + pv.x, acc[t].y + pv.y, acc[t].z + pv.z, acc[t].w + pv.w};
                *(float4*)(qout + ((size_t)b * TT + t0 + t) * HH + hc * 4) = o;
            }
        }
    }
}

// ---------------- final: fused q@Wq + score (unmasked); 8 t/block ----------------
__global__ void __launch_bounds__(256) final_kernel(
    const float* __restrict__ qin, const float* __restrict__ wq,
    const float* __restrict__ feat, const float* __restrict__ v,
    float* __restrict__ out)
{
    __shared__ float buf[8 * HH];
    __shared__ float qsm[8 * HH];
    __shared__ float vsm[HH];

    const int tg = blockIdx.x, b = blockIdx.y, tid = threadIdx.x;
    const int t0 = tg * 8;

    {
        const float4* qsrc = (const float4*)(qin + ((size_t)b * TT + t0) * HH);
        float4* qdst = (float4*)buf;
#pragma unroll
        for (int i = 0; i < 4; i++) qdst[tid + 256 * i] = qsrc[tid + 256 * i];
        vsm[tid] = v[tid]; vsm[tid + 256] = v[tid + 256];
    }
    __syncthreads();

    {
        float acc0[8] = {}, acc1[8] = {};
        const float* wqp = wq + tid;
        for (int k = 0; k < HH; k += 2) {
            float w0a = wqp[(size_t)k * HH];
            float w1a = wqp[(size_t)k * HH + 256];
            float w0b = wqp[(size_t)(k + 1) * HH];
            float w1b = wqp[(size_t)(k + 1) * HH + 256];
#pragma unroll
            for (int t = 0; t < 8; t++) {
                float qa_ = buf[t * HH + k];
                float qb_ = buf[t * HH + k + 1];
                acc0[t] = fmaf(qa_, w0a, fmaf(qb_, w0b, acc0[t]));
                acc1[t] = fmaf(qa_, w1a, fmaf(qb_, w1b, acc1[t]));
            }
        }
#pragma unroll
        for (int t = 0; t < 8; t++) {
            qsm[t * HH + tid]       = acc0[t];
            qsm[t * HH + tid + 256] = acc1[t];
        }
    }
    __syncthreads();

    const int wid = tid >> 5, lane = tid & 31;
    const float* qt = qsm + wid * HH;
    for (int n = 0; n < NSS; n++) {
        const float* f = feat + ((size_t)b * NSS + n) * HH;
        float s = 0.f;
#pragma unroll 4
        for (int j = 0; j < 16; j++) {
            int k = lane + (j << 5);
            s += vsm[k] * fast_tanh(f[k] + qt[k]);
        }
#pragma unroll
        for (int o = 16; o; o >>= 1) s += __shfl_xor_sync(0xffffffffu, s, o);
        if (lane == 0) out[((size_t)b * TT + t0 + wid) * NSS + n] = s;
    }
}

extern "C" void kernel_launch(void* const* d_in, const int* in_sizes, int n_in,
                              void* d_out, int out_size)
{
    const float* attn_mem = (const float*)d_in[0];
    const float* lstm_in  = (const float*)d_in[1];
    const float* init_h   = (const float*)d_in[2];
    const float* init_c   = (const float*)d_in[3];
    const float* Wih      = (const float*)d_in[4];
    const float* Whh      = (const float*)d_in[5];
    const float* bih      = (const float*)d_in[6];
    const float* bhh      = (const float*)d_in[7];
    const float* attn_wm  = (const float*)d_in[8];
    const float* attn_wq  = (const float*)d_in[9];
    const float* attn_v   = (const float*)d_in[10];
    const float* hop_wm   = (const float*)d_in[11];
    const float* hop_wq   = (const float*)d_in[12];
    const float* hop_v    = (const float*)d_in[13];
    const int*   msz      = (const int*)d_in[14];
    float* out = (float*)d_out;

    float *afeat, *hfeat, *xcat, *X, *qa, *qb;
    cudaGetSymbolAddress((void**)&afeat, g_attn_feat);
    cudaGetSymbolAddress((void**)&hfeat, g_hop_feat);
    cudaGetSymbolAddress((void**)&xcat,  g_xcat);
    cudaGetSymbolAddress((void**)&X,     g_X);
    cudaGetSymbolAddress((void**)&qa,    g_qa);
    cudaGetSymbolAddress((void**)&qb,    g_qb);

    prep_kernel<<<dim3(TT, BB), DD>>>(attn_mem, lstm_in, init_h, msz);
    sgemm_big<false,false><<<dim3(4, 16, 2), 256>>>(attn_mem, attn_wm, hop_wm,
                                                    nullptr, nullptr, afeat, hfeat,
                                                    BB*NSS, HH, DD);
    sgemm_big<true, true ><<<dim3(16, 8, 1), 256>>>(xcat, Wih, nullptr,
                                                    bih, bhh, X, nullptr,
                                                    TT*BB, 4*HH, DD);
    lstm_kernel<<<NB_LSTM, 256>>>(Whh, init_c);
    hop_kernel<<<dim3(8, BB), 256>>>(qa, hop_wq, hfeat, hop_v, msz, qb);
    hop_kernel<<<dim3(8, BB), 256>>>(qb, hop_wq, hfeat, hop_v, msz, qa);
    final_kernel<<<dim3(8, BB), 256>>>(qa, attn_wq, afeat, attn_v, out);
}

// round 12
// speedup vs baseline: 1.2033x; 1.2033x over previous
#include <cuda_runtime.h>
#include <cstdint>

#define BB   16
#define NSS  128
#define TT   64
#define DD   512
#define HH   512
#define NB_LSTM 128

// ---------------- scratch (device globals) ----------------
__device__ float g_attn_feat[BB * NSS * HH];
__device__ float g_hop_feat [BB * NSS * HH];
__device__ float g_xcat     [TT * BB * DD];      // row = t*16+b
__device__ float g_X        [TT * BB * 4 * HH];  // gate preacts
__device__ float g_qa       [BB * TT * HH];      // row = b*64+t
__device__ float g_qb       [BB * TT * HH];
__device__ float g_qw       [BB * TT * HH];
__device__ float g_hbuf     [2][BB * HH];
__device__ unsigned g_cnt8  [TT][512];           // 8 counters/step @256B stride

// ---------------- helpers ----------------
__device__ __forceinline__ float fast_tanh(float x) {
    float e, r;
    asm("ex2.approx.f32 %0, %1;" : "=f"(e) : "f"(x * 2.885390081777927f));
    asm("rcp.approx.f32 %0, %1;" : "=f"(r) : "f"(e + 1.0f));
    return fmaf(-2.0f, r, 1.0f);
}
__device__ __forceinline__ float sigm(float x) { return 1.0f / (1.0f + __expf(-x)); }

__device__ __forceinline__ unsigned long long ffma2(
    unsigned long long a, unsigned long long b, unsigned long long c) {
    unsigned long long d;
    asm("fma.rn.f32x2 %0, %1, %2, %3;" : "=l"(d) : "l"(a), "l"(b), "l"(c));
    return d;
}
__device__ __forceinline__ unsigned long long pack2(float a) {
    unsigned long long d;
    asm("mov.b64 %0, {%1, %1};" : "=l"(d) : "f"(a));
    return d;
}
__device__ __forceinline__ float2 unpack2(unsigned long long v) {
    float lo, hi;
    asm("mov.b64 {%0, %1}, %2;" : "=f"(lo), "=f"(hi) : "l"(v));
    return make_float2(lo, hi);
}
__device__ __forceinline__ float pairsum(unsigned long long v) {
    float2 p = unpack2(v);
    return p.x + p.y;
}
__device__ __forceinline__ void atom_add_release(unsigned* p) {
    unsigned old;
    asm volatile("atom.release.gpu.global.add.u32 %0, [%1], 1;"
                 : "=r"(old) : "l"(p) : "memory");
}
__device__ __forceinline__ unsigned ld_acquire(const unsigned* p) {
    unsigned v;
    asm volatile("ld.acquire.gpu.global.u32 %0, [%1];" : "=r"(v) : "l"(p) : "memory");
    return v;
}

// ============ BIG SGEMM: 128x128 tile, BK=8, 256 threads, 8x8 micro, f32x2 ============
#define SBS 132
template<bool TRANSB, bool BIAS>
__global__ void __launch_bounds__(256) sgemm_big(
    const float* __restrict__ A,
    const float* __restrict__ B0, const float* __restrict__ B1,
    const float* __restrict__ bi1, const float* __restrict__ bi2,
    float* __restrict__ C0, float* __restrict__ C1,
    int M, int N, int K)
{
    const float* __restrict__ Bm = blockIdx.z ? B1 : B0;
    float* __restrict__ C = blockIdx.z ? C1 : C0;

    __shared__ float As[2][8 * SBS];
    __shared__ float Bs[2][8 * SBS];

    const int tid = threadIdx.x;
    const int m0 = blockIdx.y * 128, n0 = blockIdx.x * 128;
    const int row0 = (tid >> 4) << 3;
    const int col0 = (tid & 15) << 3;

    const int am = tid >> 1, akq = (tid & 1) << 2;
    const float* Ap = A + (size_t)(m0 + am) * K + akq;
    int bn = 0, bkq = 0, bkr = 0, bn4 = 0;
    const float* Bp;
    if (TRANSB) { bn = tid >> 1; bkq = (tid & 1) << 2; Bp = Bm + (size_t)(n0 + bn) * K + bkq; }
    else        { bkr = tid >> 5; bn4 = (tid & 31) << 2; Bp = Bm + (size_t)bkr * N + n0 + bn4; }

    unsigned long long acc2[8][4];
#pragma unroll
    for (int i = 0; i < 8; i++)
#pragma unroll
        for (int j = 0; j < 4; j++) acc2[i][j] = 0ULL;

    float4 av, bv;
    av = *(const float4*)(Ap);
    bv = *(const float4*)(Bp);
    {
        float* as = As[0];
        as[(akq+0)*SBS + am] = av.x; as[(akq+1)*SBS + am] = av.y;
        as[(akq+2)*SBS + am] = av.z; as[(akq+3)*SBS + am] = av.w;
        float* bs = Bs[0];
        if (TRANSB) {
            bs[(bkq+0)*SBS + bn] = bv.x; bs[(bkq+1)*SBS + bn] = bv.y;
            bs[(bkq+2)*SBS + bn] = bv.z; bs[(bkq+3)*SBS + bn] = bv.w;
        } else {
            *(float4*)(bs + bkr*SBS + bn4) = bv;
        }
    }
    __syncthreads();

    int buf = 0;
    for (int k0 = 8; k0 <= K; k0 += 8) {
        const bool more = (k0 < K);
        if (more) {
            av = *(const float4*)(Ap + k0);
            if (TRANSB) bv = *(const float4*)(Bp + k0);
            else        bv = *(const float4*)(Bm + (size_t)(k0 + bkr) * N + n0 + bn4);
        }
        const float* as = As[buf];
        const float* bs = Bs[buf];
#pragma unroll
        for (int kk = 0; kk < 8; kk++) {
            float4 a0 = *(const float4*)(as + kk*SBS + row0);
            float4 a1 = *(const float4*)(as + kk*SBS + row0 + 4);
            ulonglong2 b01 = *(const ulonglong2*)(bs + kk*SBS + col0);      // (b0,b1),(b2,b3)
            ulonglong2 b23 = *(const ulonglong2*)(bs + kk*SBS + col0 + 4);  // (b4,b5),(b6,b7)
            float aa[8] = {a0.x,a0.y,a0.z,a0.w,a1.x,a1.y,a1.z,a1.w};
#pragma unroll
            for (int i = 0; i < 8; i++) {
                unsigned long long ad = pack2(aa[i]);
                acc2[i][0] = ffma2(ad, b01.x, acc2[i][0]);
                acc2[i][1] = ffma2(ad, b01.y, acc2[i][1]);
                acc2[i][2] = ffma2(ad, b23.x, acc2[i][2]);
                acc2[i][3] = ffma2(ad, b23.y, acc2[i][3]);
            }
        }
        if (more) {
            float* asn = As[buf ^ 1];
            asn[(akq+0)*SBS + am] = av.x; asn[(akq+1)*SBS + am] = av.y;
            asn[(akq+2)*SBS + am] = av.z; asn[(akq+3)*SBS + am] = av.w;
            float* bsn = Bs[buf ^ 1];
            if (TRANSB) {
                bsn[(bkq+0)*SBS + bn] = bv.x; bsn[(bkq+1)*SBS + bn] = bv.y;
                bsn[(bkq+2)*SBS + bn] = bv.z; bsn[(bkq+3)*SBS + bn] = bv.w;
            } else {
                *(float4*)(bsn + bkr*SBS + bn4) = bv;
            }
        }
        __syncthreads();
        buf ^= 1;
    }

    float bias[8] = {};
    if (BIAS) {
#pragma unroll
        for (int j = 0; j < 8; j++) bias[j] = bi1[n0+col0+j] + bi2[n0+col0+j];
    }
#pragma unroll
    for (int i = 0; i < 8; i++) {
        float2 p0 = unpack2(acc2[i][0]);
        float2 p1 = unpack2(acc2[i][1]);
        float2 p2 = unpack2(acc2[i][2]);
        float2 p3 = unpack2(acc2[i][3]);
        float4 o0 = {p0.x+bias[0], p0.y+bias[1], p1.x+bias[2], p1.y+bias[3]};
        float4 o1 = {p2.x+bias[4], p2.y+bias[5], p3.x+bias[6], p3.y+bias[7]};
        float* cp = C + (size_t)(m0 + row0 + i) * N + n0 + col0;
        *(float4*)(cp)     = o0;
        *(float4*)(cp + 4) = o1;
    }
}

// ============ SMALL SGEMM: 64x64 tile, 256 threads, 4x4 micro ============
__global__ void __launch_bounds__(256) sgemm_small(
    const float* __restrict__ A, const float* __restrict__ Bm,
    float* __restrict__ C, int M, int N, int K)
{
    __shared__ float As[16][68];
    __shared__ float Bs[16][68];
    const int tid = threadIdx.x;
    const int m0 = blockIdx.y * 64, n0 = blockIdx.x * 64;
    const int tx = (tid & 15) << 2, ty = (tid >> 4) << 2;
    const int lr = tid >> 2, lk = (tid & 3) << 2;
    const int bkr = tid >> 4, bnc = (tid & 15) << 2;
    float acc[4][4] = {};

    for (int k0 = 0; k0 < K; k0 += 16) {
        float4 av = *(const float4*)(A + (size_t)(m0 + lr) * K + k0 + lk);
        As[lk+0][lr] = av.x; As[lk+1][lr] = av.y; As[lk+2][lr] = av.z; As[lk+3][lr] = av.w;
        float4 bv = *(const float4*)(Bm + (size_t)(k0 + bkr) * N + n0 + bnc);
        *(float4*)(&Bs[bkr][bnc]) = bv;
        __syncthreads();
#pragma unroll
        for (int kk = 0; kk < 16; kk++) {
            float4 a = *(const float4*)(&As[kk][ty]);
            float4 b = *(const float4*)(&Bs[kk][tx]);
            acc[0][0] += a.x*b.x; acc[0][1] += a.x*b.y; acc[0][2] += a.x*b.z; acc[0][3] += a.x*b.w;
            acc[1][0] += a.y*b.x; acc[1][1] += a.y*b.y; acc[1][2] += a.y*b.z; acc[1][3] += a.y*b.w;
            acc[2][0] += a.z*b.x; acc[2][1] += a.z*b.y; acc[2][2] += a.z*b.z; acc[2][3] += a.z*b.w;
            acc[3][0] += a.w*b.x; acc[3][1] += a.w*b.y; acc[3][2] += a.w*b.z; acc[3][3] += a.w*b.w;
        }
        __syncthreads();
    }
#pragma unroll
    for (int i = 0; i < 4; i++) {
        float4 o = {acc[i][0], acc[i][1], acc[i][2], acc[i][3]};
        *(float4*)(C + (size_t)(m0+ty+i) * N + n0 + tx) = o;
    }
}

// ---------------- prep: xcat + maxpool + h0 + counter reset ----------------
__global__ void prep_kernel(const float* __restrict__ attn_mem,
                            const float* __restrict__ lstm_in,
                            const float* __restrict__ init_h,
                            const int* __restrict__ msz)
{
    const int t = blockIdx.x, b = blockIdx.y, d = threadIdx.x;
    if (b == 0) g_cnt8[t][d] = 0u;
    if (t == 0) {
        const int ms = msz[b];
        float m = -3.0e38f;
        for (int n = 0; n < ms; n++)
            m = fmaxf(m, attn_mem[((size_t)b * NSS + n) * DD + d]);
        g_xcat[(size_t)b * DD + d] = m;
        g_hbuf[0][b * HH + d] = init_h[d];
    } else {
        g_xcat[((size_t)t * BB + b) * DD + d] =
            lstm_in[((size_t)b * (TT - 1) + (t - 1)) * DD + d];
    }
}

// ---------------- persistent LSTM: 128 CTAs, split release/acquire barrier ----------------
__global__ void __launch_bounds__(256) lstm_kernel(const float* __restrict__ Whh,
                                                   const float* __restrict__ init_c)
{
    __shared__ float h_sm[16][516];        // 33 KB; aliased as red after compute
    __shared__ float gsm[16][16];
    __shared__ float c_sm[16][4];

    float* red = &h_sm[0][0];              // [16 kc][260] scratch (aliased)

    const int tid = threadIdx.x;
    const int cta = blockIdx.x;
    const int hd0 = cta * 4;
    const int kc = tid & 15;
    const int rr = (tid >> 4) & 3;
    const int bq = tid >> 6;

    const float* wp0 = Whh + ((size_t)(0*HH + hd0 + rr)) * HH + kc * 4;
    const float* wp1 = Whh + ((size_t)(1*HH + hd0 + rr)) * HH + kc * 4;
    const float* wp2 = Whh + ((size_t)(2*HH + hd0 + rr)) * HH + kc * 4;
    const float* wp3 = Whh + ((size_t)(3*HH + hd0 + rr)) * HH + kc * 4;

    if (tid < 64) { int b = tid >> 2, l = tid & 3; c_sm[b][l] = init_c[hd0 + l]; }

    const int rowX = tid >> 4;
    const int bX   = tid & 15;

    for (int s = 0; s < TT; s++) {
        float xv = __ldcg(&g_X[((size_t)s * BB + bX) * (4 * HH) + (rowX >> 2) * HH + hd0 + (rowX & 3)]);

        if (s > 0) {
            if (tid < 8) {
                while (ld_acquire(&g_cnt8[s - 1][tid * 64]) < 16u) { }
            }
        }
        __syncthreads();

        const float4* hb = (const float4*)g_hbuf[s & 1];
#pragma unroll
        for (int i2 = 0; i2 < 8; i2++) {
            int i = tid + 256 * i2;
            float4 hv = __ldcg(hb + i);
            int b = i >> 7, k4 = (i & 127) << 2;
            *(float4*)(&h_sm[b][k4]) = hv;
        }
        __syncthreads();

        unsigned long long acc[4][4];
#pragma unroll
        for (int g = 0; g < 4; g++)
#pragma unroll
            for (int bi = 0; bi < 4; bi++) acc[g][bi] = 0ULL;

#pragma unroll
        for (int j = 0; j < 8; j++) {
            const ulonglong2 w0 = *(const ulonglong2*)(wp0 + j * 64);
            const ulonglong2 w1 = *(const ulonglong2*)(wp1 + j * 64);
            const ulonglong2 w2 = *(const ulonglong2*)(wp2 + j * 64);
            const ulonglong2 w3 = *(const ulonglong2*)(wp3 + j * 64);
#pragma unroll
            for (int bi = 0; bi < 4; bi++) {
                const ulonglong2 h2 = *(const ulonglong2*)(&h_sm[bq * 4 + bi][kc * 4 + j * 64]);
                acc[0][bi] = ffma2(w0.x, h2.x, acc[0][bi]);
                acc[0][bi] = ffma2(w0.y, h2.y, acc[0][bi]);
                acc[1][bi] = ffma2(w1.x, h2.x, acc[1][bi]);
                acc[1][bi] = ffma2(w1.y, h2.y, acc[1][bi]);
                acc[2][bi] = ffma2(w2.x, h2.x, acc[2][bi]);
                acc[2][bi] = ffma2(w2.y, h2.y, acc[2][bi]);
                acc[3][bi] = ffma2(w3.x, h2.x, acc[3][bi]);
                acc[3][bi] = ffma2(w3.y, h2.y, acc[3][bi]);
            }
        }
        __syncthreads();

#pragma unroll
        for (int g = 0; g < 4; g++)
#pragma unroll
            for (int bi = 0; bi < 4; bi++)
                red[kc * 260 + (g * 4 + rr) * 16 + (bq * 4 + bi)] = pairsum(acc[g][bi]);
        __syncthreads();

        {
            float sum = xv;
#pragma unroll
            for (int i = 0; i < 16; i++) sum += red[i * 260 + rowX * 16 + bX];
            gsm[rowX][bX] = sum;
        }
        __syncthreads();

        if (tid < 64) {
            int b = tid >> 2, l = tid & 3;
            float gi = gsm[0 + l][b], gf = gsm[4 + l][b];
            float gg = gsm[8 + l][b], go = gsm[12 + l][b];
            float c = sigm(gf) * c_sm[b][l] + sigm(gi) * fast_tanh(gg);
            float h = sigm(go) * fast_tanh(c);
            c_sm[b][l] = c;
            g_hbuf[(s + 1) & 1][b * HH + hd0 + l] = h;
            g_qa[((size_t)b * TT + s) * HH + hd0 + l] = h;
        }
        __syncthreads();
        if (tid == 0 && s < TT - 1) {
            atom_add_release(&g_cnt8[s][(cta & 7) * 64]);
        }
    }
}

// ---------------- hop: 8 t per block; score+softmax+weighted-sum fused ----------------
__global__ void __launch_bounds__(256) hop_kernel(
    const float* __restrict__ qw, const float* __restrict__ feat,
    const float* __restrict__ v, const int* __restrict__ msz,
    float* __restrict__ qout)
{
    __shared__ float qsm[8 * HH];
    __shared__ float vsm[HH];
    __shared__ float p[8][NSS];
    __shared__ float4 part[8][HH / 4];

    const int tg = blockIdx.x, b = blockIdx.y, tid = threadIdx.x;
    const int t0 = tg * 8;
    const float* qbase = qw + ((size_t)b * TT + t0) * HH;
    {
        const float4* qsrc = (const float4*)qbase;
        float4* qdst = (float4*)qsm;
#pragma unroll
        for (int i = 0; i < 4; i++) qdst[tid + 256 * i] = qsrc[tid + 256 * i];
        vsm[tid] = v[tid]; vsm[tid + 256] = v[tid + 256];
    }
    __syncthreads();

    const int wid = tid >> 5, lane = tid & 31;
    const int ms = msz[b];
    const float* qt = qsm + wid * HH;
    for (int n = 0; n < NSS; n++) {
        const float* f = feat + ((size_t)b * NSS + n) * HH;
        float s = 0.f;
#pragma unroll 4
        for (int j = 0; j < 16; j++) {
            int k = lane + (j << 5);
            s += vsm[k] * fast_tanh(f[k] + qt[k]);
        }
#pragma unroll
        for (int o = 16; o; o >>= 1) s += __shfl_xor_sync(0xffffffffu, s, o);
        if (lane == 0) p[wid][n] = (n < ms) ? s : -1e30f;
    }
    __syncthreads();
    {
        float x0 = p[wid][lane], x1 = p[wid][lane+32], x2 = p[wid][lane+64], x3 = p[wid][lane+96];
        float m = fmaxf(fmaxf(x0, x1), fmaxf(x2, x3));
#pragma unroll
        for (int o = 16; o; o >>= 1) m = fmaxf(m, __shfl_xor_sync(0xffffffffu, m, o));
        float e0 = __expf(x0 - m), e1 = __expf(x1 - m), e2 = __expf(x2 - m), e3 = __expf(x3 - m);
        float s = e0 + e1 + e2 + e3;
#pragma unroll
        for (int o = 16; o; o >>= 1) s += __shfl_xor_sync(0xffffffffu, s, o);
        float inv = 1.f / s;
        p[wid][lane] = e0*inv; p[wid][lane+32] = e1*inv; p[wid][lane+64] = e2*inv; p[wid][lane+96] = e3*inv;
    }
    __syncthreads();
    {
        const int g = tid >> 7;
        const int hc = tid & 127;
        float4 acc[8] = {};
        const int nlo = g * 64;
#pragma unroll 2
        for (int n = nlo; n < nlo + 64; n++) {
            float4 fv = *(const float4*)(feat + ((size_t)b * NSS + n) * HH + hc * 4);
#pragma unroll
            for (int t = 0; t < 8; t++) {
                float pw = p[t][n];
                acc[t].x = fmaf(pw, fv.x, acc[t].x);
                acc[t].y = fmaf(pw, fv.y, acc[t].y);
                acc[t].z = fmaf(pw, fv.z, acc[t].z);
                acc[t].w = fmaf(pw, fv.w, acc[t].w);
            }
        }
        if (g == 1) {
#pragma unroll
            for (int t = 0; t < 8; t++) part[t][hc] = acc[t];
        }
        __syncthreads();
        if (g == 0) {
#pragma unroll
            for (int t = 0; t < 8; t++) {
                float4 pv = part[t][hc];
                float4 o = {acc[t].x + pv.x, acc[t].y + pv.y, acc[t].z + pv.z, acc[t].w + pv.w};
                *(float4*)(qout + ((size_t)b * TT + t0 + t) * HH + hc * 4) = o;
            }
        }
    }
}

// ---------------- final score (unmasked) ----------------
__global__ void __launch_bounds__(256) final_kernel(
    const float* __restrict__ qw, const float* __restrict__ feat,
    const float* __restrict__ v, float* __restrict__ out)
{
    __shared__ float qsm[HH];
    __shared__ float vsm[HH];
    const int t = blockIdx.x, b = blockIdx.y, tid = threadIdx.x;
    const float* qrow = qw + ((size_t)b * TT + t) * HH;
    qsm[tid] = qrow[tid]; qsm[tid + 256] = qrow[tid + 256];
    vsm[tid] = v[tid];    vsm[tid + 256] = v[tid + 256];
    __syncthreads();
    const int wid = tid >> 5, lane = tid & 31;
    for (int n = wid; n < NSS; n += 8) {
        const float* f = feat + ((size_t)b * NSS + n) * HH;
        float s = 0.f;
#pragma unroll 4
        for (int j = 0; j < 16; j++) {
            int k = lane + (j << 5);
            s += vsm[k] * fast_tanh(f[k] + qsm[k]);
        }
#pragma unroll
        for (int o = 16; o; o >>= 1) s += __shfl_xor_sync(0xffffffffu, s, o);
        if (lane == 0) out[(((size_t)b * TT) + t) * NSS + n] = s;
    }
}

extern "C" void kernel_launch(void* const* d_in, const int* in_sizes, int n_in,
                              void* d_out, int out_size)
{
    const float* attn_mem = (const float*)d_in[0];
    const float* lstm_in  = (const float*)d_in[1];
    const float* init_h   = (const float*)d_in[2];
    const float* init_c   = (const float*)d_in[3];
    const float* Wih      = (const float*)d_in[4];
    const float* Whh      = (const float*)d_in[5];
    const float* bih      = (const float*)d_in[6];
    const float* bhh      = (const float*)d_in[7];
    const float* attn_wm  = (const float*)d_in[8];
    const float* attn_wq  = (const float*)d_in[9];
    const float* attn_v   = (const float*)d_in[10];
    const float* hop_wm   = (const float*)d_in[11];
    const float* hop_wq   = (const float*)d_in[12];
    const float* hop_v    = (const float*)d_in[13];
    const int*   msz      = (const int*)d_in[14];
    float* out = (float*)d_out;

    float *afeat, *hfeat, *xcat, *X, *qa, *qb, *qwb;
    cudaGetSymbolAddress((void**)&afeat, g_attn_feat);
    cudaGetSymbolAddress((void**)&hfeat, g_hop_feat);
    cudaGetSymbolAddress((void**)&xcat,  g_xcat);
    cudaGetSymbolAddress((void**)&X,     g_X);
    cudaGetSymbolAddress((void**)&qa,    g_qa);
    cudaGetSymbolAddress((void**)&qb,    g_qb);
    cudaGetSymbolAddress((void**)&qwb,   g_qw);

    prep_kernel<<<dim3(TT, BB), DD>>>(attn_mem, lstm_in, init_h, msz);
    sgemm_big<false,false><<<dim3(4, 16, 2), 256>>>(attn_mem, attn_wm, hop_wm,
                                                    nullptr, nullptr, afeat, hfeat,
                                                    BB*NSS, HH, DD);
    sgemm_big<true, true ><<<dim3(16, 8, 1), 256>>>(xcat, Wih, nullptr,
                                                    bih, bhh, X, nullptr,
                                                    TT*BB, 4*HH, DD);
    lstm_kernel<<<NB_LSTM, 256>>>(Whh, init_c);
    // hop 1
    sgemm_small<<<dim3(8, 16), 256>>>(qa, hop_wq, qwb, BB*TT, HH, HH);
    hop_kernel<<<dim3(8, BB), 256>>>(qwb, hfeat, hop_v, msz, qb);
    // hop 2
    sgemm_small<<<dim3(8, 16), 256>>>(qb, hop_wq, qwb, BB*TT, HH, HH);
    hop_kernel<<<dim3(8, BB), 256>>>(qwb, hfeat, hop_v, msz, qa);
    // final
    sgemm_small<<<dim3(8, 16), 256>>>(qa, attn_wq, qwb, BB*TT, HH, HH);
    final_kernel<<<dim3(TT, BB), 256>>>(qwb, afeat, attn_v, out);
}

// round 13
// speedup vs baseline: 1.2442x; 1.0341x over previous
#include <cuda_runtime.h>
#include <cstdint>

#define BB   16
#define NSS  128
#define TT   64
#define DD   512
#define HH   512
#define NB_LSTM 128

// ---------------- scratch (device globals) ----------------
__device__ float g_attn_feat[BB * NSS * HH];
__device__ float g_hop_feat [BB * NSS * HH];
__device__ float g_xcat     [TT * BB * DD];      // row = t*16+b
__device__ float g_X        [TT * BB * 4 * HH];  // gate preacts
__device__ float g_qa       [BB * TT * HH];      // row = b*64+t
__device__ float g_qb       [BB * TT * HH];
__device__ float g_qw       [BB * TT * HH];
__device__ float g_hbuf     [2][BB * HH];
__device__ unsigned g_cnt8  [TT][512];           // 8 counters/step @256B stride

// ---------------- helpers ----------------
__device__ __forceinline__ float fast_tanh(float x) {
    float e, r;
    asm("ex2.approx.f32 %0, %1;" : "=f"(e) : "f"(x * 2.885390081777927f));
    asm("rcp.approx.f32 %0, %1;" : "=f"(r) : "f"(e + 1.0f));
    return fmaf(-2.0f, r, 1.0f);
}
__device__ __forceinline__ float sigm(float x) { return 1.0f / (1.0f + __expf(-x)); }

__device__ __forceinline__ unsigned long long ffma2(
    unsigned long long a, unsigned long long b, unsigned long long c) {
    unsigned long long d;
    asm("fma.rn.f32x2 %0, %1, %2, %3;" : "=l"(d) : "l"(a), "l"(b), "l"(c));
    return d;
}
__device__ __forceinline__ unsigned long long pack2(float a) {
    unsigned long long d;
    asm("mov.b64 %0, {%1, %1};" : "=l"(d) : "f"(a));
    return d;
}
__device__ __forceinline__ float2 unpack2(unsigned long long v) {
    float lo, hi;
    asm("mov.b64 {%0, %1}, %2;" : "=f"(lo), "=f"(hi) : "l"(v));
    return make_float2(lo, hi);
}
__device__ __forceinline__ float pairsum(unsigned long long v) {
    float2 p = unpack2(v);
    return p.x + p.y;
}
__device__ __forceinline__ void atom_add_release(unsigned* p) {
    unsigned old;
    asm volatile("atom.release.gpu.global.add.u32 %0, [%1], 1;"
                 : "=r"(old) : "l"(p) : "memory");
}
__device__ __forceinline__ unsigned ld_acquire(const unsigned* p) {
    unsigned v;
    asm volatile("ld.acquire.gpu.global.u32 %0, [%1];" : "=r"(v) : "l"(p) : "memory");
    return v;
}

#define SBS 132

// ---------------- shared-memory overlays for the combined kernel ----------------
struct SmemLstm {
    float h_sm[16][516];   // aliased as red[16][260] after compute
    float gsm[16][16];
    float c_sm[16][4];
};
struct SmemGemm {
    float As[2][8 * SBS];
    float Bs[2][8 * SBS];
};
union SmemU { SmemLstm l; SmemGemm g; };

// ============ standalone BIG SGEMM (Wih): 128x128 tile, BK=8, TRANSB+BIAS ============
__global__ void __launch_bounds__(256) sgemm_wih(
    const float* __restrict__ A, const float* __restrict__ Bm,
    const float* __restrict__ bi1, const float* __restrict__ bi2,
    float* __restrict__ C, int M, int N, int K)
{
    __shared__ float As[2][8 * SBS];
    __shared__ float Bs[2][8 * SBS];

    const int tid = threadIdx.x;
    const int m0 = blockIdx.y * 128, n0 = blockIdx.x * 128;
    const int row0 = (tid >> 4) << 3;
    const int col0 = (tid & 15) << 3;

    const int am = tid >> 1, akq = (tid & 1) << 2;
    const float* Ap = A + (size_t)(m0 + am) * K + akq;
    const int bn = tid >> 1, bkq = (tid & 1) << 2;
    const float* Bp = Bm + (size_t)(n0 + bn) * K + bkq;

    unsigned long long acc2[8][4];
#pragma unroll
    for (int i = 0; i < 8; i++)
#pragma unroll
        for (int j = 0; j < 4; j++) acc2[i][j] = 0ULL;

    float4 av = *(const float4*)(Ap);
    float4 bv = *(const float4*)(Bp);
    {
        float* as = As[0];
        as[(akq+0)*SBS + am] = av.x; as[(akq+1)*SBS + am] = av.y;
        as[(akq+2)*SBS + am] = av.z; as[(akq+3)*SBS + am] = av.w;
        float* bs = Bs[0];
        bs[(bkq+0)*SBS + bn] = bv.x; bs[(bkq+1)*SBS + bn] = bv.y;
        bs[(bkq+2)*SBS + bn] = bv.z; bs[(bkq+3)*SBS + bn] = bv.w;
    }
    __syncthreads();

    int buf = 0;
    for (int k0 = 8; k0 <= K; k0 += 8) {
        const bool more = (k0 < K);
        if (more) {
            av = *(const float4*)(Ap + k0);
            bv = *(const float4*)(Bp + k0);
        }
        const float* as = As[buf];
        const float* bs = Bs[buf];
#pragma unroll
        for (int kk = 0; kk < 8; kk++) {
            float4 a0 = *(const float4*)(as + kk*SBS + row0);
            float4 a1 = *(const float4*)(as + kk*SBS + row0 + 4);
            ulonglong2 b01 = *(const ulonglong2*)(bs + kk*SBS + col0);
            ulonglong2 b23 = *(const ulonglong2*)(bs + kk*SBS + col0 + 4);
            float aa[8] = {a0.x,a0.y,a0.z,a0.w,a1.x,a1.y,a1.z,a1.w};
#pragma unroll
            for (int i = 0; i < 8; i++) {
                unsigned long long ad = pack2(aa[i]);
                acc2[i][0] = ffma2(ad, b01.x, acc2[i][0]);
                acc2[i][1] = ffma2(ad, b01.y, acc2[i][1]);
                acc2[i][2] = ffma2(ad, b23.x, acc2[i][2]);
                acc2[i][3] = ffma2(ad, b23.y, acc2[i][3]);
            }
        }
        if (more) {
            float* asn = As[buf ^ 1];
            asn[(akq+0)*SBS + am] = av.x; asn[(akq+1)*SBS + am] = av.y;
            asn[(akq+2)*SBS + am] = av.z; asn[(akq+3)*SBS + am] = av.w;
            float* bsn = Bs[buf ^ 1];
            bsn[(bkq+0)*SBS + bn] = bv.x; bsn[(bkq+1)*SBS + bn] = bv.y;
            bsn[(bkq+2)*SBS + bn] = bv.z; bsn[(bkq+3)*SBS + bn] = bv.w;
        }
        __syncthreads();
        buf ^= 1;
    }

    float bias[8];
#pragma unroll
    for (int j = 0; j < 8; j++) bias[j] = bi1[n0+col0+j] + bi2[n0+col0+j];
#pragma unroll
    for (int i = 0; i < 8; i++) {
        float2 p0 = unpack2(acc2[i][0]);
        float2 p1 = unpack2(acc2[i][1]);
        float2 p2 = unpack2(acc2[i][2]);
        float2 p3 = unpack2(acc2[i][3]);
        float4 o0 = {p0.x+bias[0], p0.y+bias[1], p1.x+bias[2], p1.y+bias[3]};
        float4 o1 = {p2.x+bias[4], p2.y+bias[5], p3.x+bias[6], p3.y+bias[7]};
        float* cp = C + (size_t)(m0 + row0 + i) * N + n0 + col0;
        *(float4*)(cp)     = o0;
        *(float4*)(cp + 4) = o1;
    }
}

// ---------------- feats gemm body (no-trans, no-bias): C=A@B, M=2048 N=512 K=512 ----------------
__device__ void feats_gemm_body(SmemGemm& S, int bx, int by,
                                const float* __restrict__ A,
                                const float* __restrict__ Bm,
                                float* __restrict__ C)
{
    const int tid = threadIdx.x;
    const int m0 = by * 128, n0 = bx * 128;
    const int N = HH, K = DD;
    const int row0 = (tid >> 4) << 3;
    const int col0 = (tid & 15) << 3;

    const int am = tid >> 1, akq = (tid & 1) << 2;
    const float* Ap = A + (size_t)(m0 + am) * K + akq;
    const int bkr = tid >> 5, bn4 = (tid & 31) << 2;
    const float* Bp = Bm + (size_t)bkr * N + n0 + bn4;

    unsigned long long acc2[8][4];
#pragma unroll
    for (int i = 0; i < 8; i++)
#pragma unroll
        for (int j = 0; j < 4; j++) acc2[i][j] = 0ULL;

    float4 av = *(const float4*)(Ap);
    float4 bv = *(const float4*)(Bp);
    {
        float* as = S.As[0];
        as[(akq+0)*SBS + am] = av.x; as[(akq+1)*SBS + am] = av.y;
        as[(akq+2)*SBS + am] = av.z; as[(akq+3)*SBS + am] = av.w;
        *(float4*)(S.Bs[0] + bkr*SBS + bn4) = bv;
    }
    __syncthreads();

    int buf = 0;
    for (int k0 = 8; k0 <= K; k0 += 8) {
        const bool more = (k0 < K);
        if (more) {
            av = *(const float4*)(Ap + k0);
            bv = *(const float4*)(Bm + (size_t)(k0 + bkr) * N + n0 + bn4);
        }
        const float* as = S.As[buf];
        const float* bs = S.Bs[buf];
#pragma unroll
        for (int kk = 0; kk < 8; kk++) {
            float4 a0 = *(const float4*)(as + kk*SBS + row0);
            float4 a1 = *(const float4*)(as + kk*SBS + row0 + 4);
            ulonglong2 b01 = *(const ulonglong2*)(bs + kk*SBS + col0);
            ulonglong2 b23 = *(const ulonglong2*)(bs + kk*SBS + col0 + 4);
            float aa[8] = {a0.x,a0.y,a0.z,a0.w,a1.x,a1.y,a1.z,a1.w};
#pragma unroll
            for (int i = 0; i < 8; i++) {
                unsigned long long ad = pack2(aa[i]);
                acc2[i][0] = ffma2(ad, b01.x, acc2[i][0]);
                acc2[i][1] = ffma2(ad, b01.y, acc2[i][1]);
                acc2[i][2] = ffma2(ad, b23.x, acc2[i][2]);
                acc2[i][3] = ffma2(ad, b23.y, acc2[i][3]);
            }
        }
        if (more) {
            float* asn = S.As[buf ^ 1];
            asn[(akq+0)*SBS + am] = av.x; asn[(akq+1)*SBS + am] = av.y;
            asn[(akq+2)*SBS + am] = av.z; asn[(akq+3)*SBS + am] = av.w;
            *(float4*)(S.Bs[buf ^ 1] + bkr*SBS + bn4) = bv;
        }
        __syncthreads();
        buf ^= 1;
    }

#pragma unroll
    for (int i = 0; i < 8; i++) {
        float2 p0 = unpack2(acc2[i][0]);
        float2 p1 = unpack2(acc2[i][1]);
        float2 p2 = unpack2(acc2[i][2]);
        float2 p3 = unpack2(acc2[i][3]);
        float4 o0 = {p0.x, p0.y, p1.x, p1.y};
        float4 o1 = {p2.x, p2.y, p3.x, p3.y};
        float* cp = C + (size_t)(m0 + row0 + i) * N + n0 + col0;
        *(float4*)(cp)     = o0;
        *(float4*)(cp + 4) = o1;
    }
}

// ---------------- lstm body (128 CTAs, split release/acquire barrier) ----------------
__device__ void lstm_body(SmemLstm& S, int cta,
                          const float* __restrict__ Whh,
                          const float* __restrict__ init_c)
{
    float* red = &S.h_sm[0][0];            // [16 kc][260] scratch (aliased)

    const int tid = threadIdx.x;
    const int hd0 = cta * 4;
    const int kc = tid & 15;
    const int rr = (tid >> 4) & 3;
    const int bq = tid >> 6;

    const float* wp0 = Whh + ((size_t)(0*HH + hd0 + rr)) * HH + kc * 4;
    const float* wp1 = Whh + ((size_t)(1*HH + hd0 + rr)) * HH + kc * 4;
    const float* wp2 = Whh + ((size_t)(2*HH + hd0 + rr)) * HH + kc * 4;
    const float* wp3 = Whh + ((size_t)(3*HH + hd0 + rr)) * HH + kc * 4;

    if (tid < 64) { int b = tid >> 2, l = tid & 3; S.c_sm[b][l] = init_c[hd0 + l]; }

    const int rowX = tid >> 4;
    const int bX   = tid & 15;

    for (int s = 0; s < TT; s++) {
        float xv = __ldcg(&g_X[((size_t)s * BB + bX) * (4 * HH) + (rowX >> 2) * HH + hd0 + (rowX & 3)]);

        if (s > 0) {
            if (tid < 8) {
                while (ld_acquire(&g_cnt8[s - 1][tid * 64]) < 16u) { }
            }
        }
        __syncthreads();

        const float4* hb = (const float4*)g_hbuf[s & 1];
#pragma unroll
        for (int i2 = 0; i2 < 8; i2++) {
            int i = tid + 256 * i2;
            float4 hv = __ldcg(hb + i);
            int b = i >> 7, k4 = (i & 127) << 2;
            *(float4*)(&S.h_sm[b][k4]) = hv;
        }
        __syncthreads();

        unsigned long long acc[4][4];
#pragma unroll
        for (int g = 0; g < 4; g++)
#pragma unroll
            for (int bi = 0; bi < 4; bi++) acc[g][bi] = 0ULL;

#pragma unroll
        for (int j = 0; j < 8; j++) {
            const ulonglong2 w0 = *(const ulonglong2*)(wp0 + j * 64);
            const ulonglong2 w1 = *(const ulonglong2*)(wp1 + j * 64);
            const ulonglong2 w2 = *(const ulonglong2*)(wp2 + j * 64);
            const ulonglong2 w3 = *(const ulonglong2*)(wp3 + j * 64);
#pragma unroll
            for (int bi = 0; bi < 4; bi++) {
                const ulonglong2 h2 = *(const ulonglong2*)(&S.h_sm[bq * 4 + bi][kc * 4 + j * 64]);
                acc[0][bi] = ffma2(w0.x, h2.x, acc[0][bi]);
                acc[0][bi] = ffma2(w0.y, h2.y, acc[0][bi]);
                acc[1][bi] = ffma2(w1.x, h2.x, acc[1][bi]);
                acc[1][bi] = ffma2(w1.y, h2.y, acc[1][bi]);
                acc[2][bi] = ffma2(w2.x, h2.x, acc[2][bi]);
                acc[2][bi] = ffma2(w2.y, h2.y, acc[2][bi]);
                acc[3][bi] = ffma2(w3.x, h2.x, acc[3][bi]);
                acc[3][bi] = ffma2(w3.y, h2.y, acc[3][bi]);
            }
        }
        __syncthreads();

#pragma unroll
        for (int g = 0; g < 4; g++)
#pragma unroll
            for (int bi = 0; bi < 4; bi++)
                red[kc * 260 + (g * 4 + rr) * 16 + (bq * 4 + bi)] = pairsum(acc[g][bi]);
        __syncthreads();

        {
            float sum = xv;
#pragma unroll
            for (int i = 0; i < 16; i++) sum += red[i * 260 + rowX * 16 + bX];
            S.gsm[rowX][bX] = sum;
        }
        __syncthreads();

        if (tid < 64) {
            int b = tid >> 2, l = tid & 3;
            float gi = S.gsm[0 + l][b], gf = S.gsm[4 + l][b];
            float gg = S.gsm[8 + l][b], go = S.gsm[12 + l][b];
            float c = sigm(gf) * S.c_sm[b][l] + sigm(gi) * fast_tanh(gg);
            float h = sigm(go) * fast_tanh(c);
            S.c_sm[b][l] = c;
            g_hbuf[(s + 1) & 1][b * HH + hd0 + l] = h;
            g_qa[((size_t)b * TT + s) * HH + hd0 + l] = h;
        }
        __syncthreads();
        if (tid == 0 && s < TT - 1) {
            atom_add_release(&g_cnt8[s][(cta & 7) * 64]);
        }
    }
}

// ---------------- combined: lstm (blocks 0-127) + feats gemm (blocks 128-255) ----------------
__global__ void __launch_bounds__(256, 2) lstm_feats_kernel(
    const float* __restrict__ Whh, const float* __restrict__ init_c,
    const float* __restrict__ attn_mem,
    const float* __restrict__ attn_wm, const float* __restrict__ hop_wm,
    float* __restrict__ afeat, float* __restrict__ hfeat)
{
    __shared__ SmemU smem;
    const int bid = blockIdx.x;
    if (bid < NB_LSTM) {
        lstm_body(smem.l, bid, Whh, init_c);
    } else {
        const int lin = bid - NB_LSTM;        // 0..127
        const int bz = lin >> 6;              // 0: attn, 1: hop
        const int rem = lin & 63;
        const int bx = rem & 3;               // 4 n-tiles (512/128)
        const int by = rem >> 2;              // 16 m-tiles (2048/128)
        feats_gemm_body(smem.g, bx, by, attn_mem,
                        bz ? hop_wm : attn_wm,
                        bz ? hfeat : afeat);
    }
}

// ============ SMALL SGEMM: 64x64 tile, 256 threads, 4x4 micro ============
__global__ void __launch_bounds__(256) sgemm_small(
    const float* __restrict__ A, const float* __restrict__ Bm,
    float* __restrict__ C, int M, int N, int K)
{
    __shared__ float As[16][68];
    __shared__ float Bs[16][68];
    const int tid = threadIdx.x;
    const int m0 = blockIdx.y * 64, n0 = blockIdx.x * 64;
    const int tx = (tid & 15) << 2, ty = (tid >> 4) << 2;
    const int lr = tid >> 2, lk = (tid & 3) << 2;
    const int bkr = tid >> 4, bnc = (tid & 15) << 2;
    float acc[4][4] = {};

    for (int k0 = 0; k0 < K; k0 += 16) {
        float4 av = *(const float4*)(A + (size_t)(m0 + lr) * K + k0 + lk);
        As[lk+0][lr] = av.x; As[lk+1][lr] = av.y; As[lk+2][lr] = av.z; As[lk+3][lr] = av.w;
        float4 bv = *(const float4*)(Bm + (size_t)(k0 + bkr) * N + n0 + bnc);
        *(float4*)(&Bs[bkr][bnc]) = bv;
        __syncthreads();
#pragma unroll
        for (int kk = 0; kk < 16; kk++) {
            float4 a = *(const float4*)(&As[kk][ty]);
            float4 b = *(const float4*)(&Bs[kk][tx]);
            acc[0][0] += a.x*b.x; acc[0][1] += a.x*b.y; acc[0][2] += a.x*b.z; acc[0][3] += a.x*b.w;
            acc[1][0] += a.y*b.x; acc[1][1] += a.y*b.y; acc[1][2] += a.y*b.z; acc[1][3] += a.y*b.w;
            acc[2][0] += a.z*b.x; acc[2][1] += a.z*b.y; acc[2][2] += a.z*b.z; acc[2][3] += a.z*b.w;
            acc[3][0] += a.w*b.x; acc[3][1] += a.w*b.y; acc[3][2] += a.w*b.z; acc[3][3] += a.w*b.w;
        }
        __syncthreads();
    }
#pragma unroll
    for (int i = 0; i < 4; i++) {
        float4 o = {acc[i][0], acc[i][1], acc[i][2], acc[i][3]};
        *(float4*)(C + (size_t)(m0+ty+i) * N + n0 + tx) = o;
    }
}

// ---------------- prep: xcat + maxpool + h0 + counter reset ----------------
__global__ void prep_kernel(const float* __restrict__ attn_mem,
                            const float* __restrict__ lstm_in,
                            const float* __restrict__ init_h,
                            const int* __restrict__ msz)
{
    const int t = blockIdx.x, b = blockIdx.y, d = threadIdx.x;
    if (b == 0) g_cnt8[t][d] = 0u;
    if (t == 0) {
        const int ms = msz[b];
        float m = -3.0e38f;
        for (int n = 0; n < ms; n++)
            m = fmaxf(m, attn_mem[((size_t)b * NSS + n) * DD + d]);
        g_xcat[(size_t)b * DD + d] = m;
        g_hbuf[0][b * HH + d] = init_h[d];
    } else {
        g_xcat[((size_t)t * BB + b) * DD + d] =
            lstm_in[((size_t)b * (TT - 1) + (t - 1)) * DD + d];
    }
}

// ---------------- hop: 8 t per block; score+softmax+weighted-sum fused ----------------
__global__ void __launch_bounds__(256) hop_kernel(
    const float* __restrict__ qw, const float* __restrict__ feat,
    const float* __restrict__ v, const int* __restrict__ msz,
    float* __restrict__ qout)
{
    __shared__ float qsm[8 * HH];
    __shared__ float vsm[HH];
    __shared__ float p[8][NSS];
    __shared__ float4 part[8][HH / 4];

    const int tg = blockIdx.x, b = blockIdx.y, tid = threadIdx.x;
    const int t0 = tg * 8;
    const float* qbase = qw + ((size_t)b * TT + t0) * HH;
    {
        const float4* qsrc = (const float4*)qbase;
        float4* qdst = (float4*)qsm;
#pragma unroll
        for (int i = 0; i < 4; i++) qdst[tid + 256 * i] = qsrc[tid + 256 * i];
        vsm[tid] = v[tid]; vsm[tid + 256] = v[tid + 256];
    }
    __syncthreads();

    const int wid = tid >> 5, lane = tid & 31;
    const int ms = msz[b];
    const float* qt = qsm + wid * HH;
    for (int n = 0; n < NSS; n++) {
        const float* f = feat + ((size_t)b * NSS + n) * HH;
        float s = 0.f;
#pragma unroll 4
        for (int j = 0; j < 16; j++) {
            int k = lane + (j << 5);
            s += vsm[k] * fast_tanh(f[k] + qt[k]);
        }
#pragma unroll
        for (int o = 16; o; o >>= 1) s += __shfl_xor_sync(0xffffffffu, s, o);
        if (lane == 0) p[wid][n] = (n < ms) ? s : -1e30f;
    }
    __syncthreads();
    {
        float x0 = p[wid][lane], x1 = p[wid][lane+32], x2 = p[wid][lane+64], x3 = p[wid][lane+96];
        float m = fmaxf(fmaxf(x0, x1), fmaxf(x2, x3));
#pragma unroll
        for (int o = 16; o; o >>= 1) m = fmaxf(m, __shfl_xor_sync(0xffffffffu, m, o));
        float e0 = __expf(x0 - m), e1 = __expf(x1 - m), e2 = __expf(x2 - m), e3 = __expf(x3 - m);
        float s = e0 + e1 + e2 + e3;
#pragma unroll
        for (int o = 16; o; o >>= 1) s += __shfl_xor_sync(0xffffffffu, s, o);
        float inv = 1.f / s;
        p[wid][lane] = e0*inv; p[wid][lane+32] = e1*inv; p[wid][lane+64] = e2*inv; p[wid][lane+96] = e3*inv;
    }
    __syncthreads();
    {
        const int g = tid >> 7;
        const int hc = tid & 127;
        float4 acc[8] = {};
        const int nlo = g * 64;
#pragma unroll 2
        for (int n = nlo; n < nlo + 64; n++) {
            float4 fv = *(const float4*)(feat + ((size_t)b * NSS + n) * HH + hc * 4);
#pragma unroll
            for (int t = 0; t < 8; t++) {
                float pw = p[t][n];
                acc[t].x = fmaf(pw, fv.x, acc[t].x);
                acc[t].y = fmaf(pw, fv.y, acc[t].y);
                acc[t].z = fmaf(pw, fv.z, acc[t].z);
                acc[t].w = fmaf(pw, fv.w, acc[t].w);
            }
        }
        if (g == 1) {
#pragma unroll
            for (int t = 0; t < 8; t++) part[t][hc] = acc[t];
        }
        __syncthreads();
        if (g == 0) {
#pragma unroll
            for (int t = 0; t < 8; t++) {
                float4 pv = part[t][hc];
                float4 o = {acc[t].x + pv.x, acc[t].y + pv.y, acc[t].z + pv.z, acc[t].w + pv.w};
                *(float4*)(qout + ((size_t)b * TT + t0 + t) * HH + hc * 4) = o;
            }
        }
    }
}

// ---------------- final score (unmasked) ----------------
__global__ void __launch_bounds__(256) final_kernel(
    const float* __restrict__ qw, const float* __restrict__ feat,
    const float* __restrict__ v, float* __restrict__ out)
{
    __shared__ float qsm[HH];
    __shared__ float vsm[HH];
    const int t = blockIdx.x, b = blockIdx.y, tid = threadIdx.x;
    const float* qrow = qw + ((size_t)b * TT + t) * HH;
    qsm[tid] = qrow[tid]; qsm[tid + 256] = qrow[tid + 256];
    vsm[tid] = v[tid];    vsm[tid + 256] = v[tid + 256];
    __syncthreads();
    const int wid = tid >> 5, lane = tid & 31;
    for (int n = wid; n < NSS; n += 8) {
        const float* f = feat + ((size_t)b * NSS + n) * HH;
        float s = 0.f;
#pragma unroll 4
        for (int j = 0; j < 16; j++) {
            int k = lane + (j << 5);
            s += vsm[k] * fast_tanh(f[k] + qsm[k]);
        }
#pragma unroll
        for (int o = 16; o; o >>= 1) s += __shfl_xor_sync(0xffffffffu, s, o);
        if (lane == 0) out[(((size_t)b * TT) + t) * NSS + n] = s;
    }
}

extern "C" void kernel_launch(void* const* d_in, const int* in_sizes, int n_in,
                              void* d_out, int out_size)
{
    const float* attn_mem = (const float*)d_in[0];
    const float* lstm_in  = (const float*)d_in[1];
    const float* init_h   = (const float*)d_in[2];
    const float* init_c   = (const float*)d_in[3];
    const float* Wih      = (const float*)d_in[4];
    const float* Whh      = (const float*)d_in[5];
    const float* bih      = (const float*)d_in[6];
    const float* bhh      = (const float*)d_in[7];
    const float* attn_wm  = (const float*)d_in[8];
    const float* attn_wq  = (const float*)d_in[9];
    const float* attn_v   = (const float*)d_in[10];
    const float* hop_wm   = (const float*)d_in[11];
    const float* hop_wq   = (const float*)d_in[12];
    const float* hop_v    = (const float*)d_in[13];
    const int*   msz      = (const int*)d_in[14];
    float* out = (float*)d_out;

    float *afeat, *hfeat, *xcat, *X, *qa, *qb, *qwb;
    cudaGetSymbolAddress((void**)&afeat, g_attn_feat);
    cudaGetSymbolAddress((void**)&hfeat, g_hop_feat);
    cudaGetSymbolAddress((void**)&xcat,  g_xcat);
    cudaGetSymbolAddress((void**)&X,     g_X);
    cudaGetSymbolAddress((void**)&qa,    g_qa);
    cudaGetSymbolAddress((void**)&qb,    g_qb);
    cudaGetSymbolAddress((void**)&qwb,   g_qw);

    prep_kernel<<<dim3(TT, BB), DD>>>(attn_mem, lstm_in, init_h, msz);
    sgemm_wih<<<dim3(16, 8), 256>>>(xcat, Wih, bih, bhh, X, TT*BB, 4*HH, DD);
    // lstm + both feat gemms co-scheduled in one launch
    lstm_feats_kernel<<<NB_LSTM + 128, 256>>>(Whh, init_c, attn_mem,
                                              attn_wm, hop_wm, afeat, hfeat);
    // hop 1
    sgemm_small<<<dim3(8, 16), 256>>>(qa, hop_wq, qwb, BB*TT, HH, HH);
    hop_kernel<<<dim3(8, BB), 256>>>(qwb, hfeat, hop_v, msz, qb);
    // hop 2
    sgemm_small<<<dim3(8, 16), 256>>>(qb, hop_wq, qwb, BB*TT, HH, HH);
    hop_kernel<<<dim3(8, BB), 256>>>(qwb, hfeat, hop_v, msz, qa);
    // final
    sgemm_small<<<dim3(8, 16), 256>>>(qa, attn_wq, qwb, BB*TT, HH, HH);
    final_kernel<<<dim3(TT, BB), 256>>>(qwb, afeat, attn_v, out);
}

// round 15
// speedup vs baseline: 1.2729x; 1.0230x over previous
#include <cuda_runtime.h>
#include <cstdint>

#define BB   16
#define NSS  128
#define TT   64
#define DD   512
#define HH   512
#define NB_LSTM 128

// ---------------- scratch (device globals) ----------------
__device__ float g_attn_feat[BB * NSS * HH];
__device__ float g_hop_feat [BB * NSS * HH];
__device__ float g_xcat     [TT * BB * DD];      // row = t*16+b
__device__ float g_X        [TT * BB * 4 * HH];  // gate preacts
__device__ float g_qa       [BB * TT * HH];      // row = b*64+t
__device__ float g_qb       [BB * TT * HH];
__device__ float g_qw       [BB * TT * HH];      // split-K partial 0
__device__ float g_qw2      [BB * TT * HH];      // split-K partial 1
__device__ float g_hbuf     [2][BB * HH];
__device__ unsigned g_cnt8  [TT][512];           // 8 counters/step @256B stride

// ---------------- helpers ----------------
__device__ __forceinline__ float fast_tanh(float x) {
    float e, r;
    asm("ex2.approx.f32 %0, %1;" : "=f"(e) : "f"(x * 2.885390081777927f));
    asm("rcp.approx.f32 %0, %1;" : "=f"(r) : "f"(e + 1.0f));
    return fmaf(-2.0f, r, 1.0f);
}
__device__ __forceinline__ float sigm(float x) { return 1.0f / (1.0f + __expf(-x)); }

__device__ __forceinline__ unsigned long long ffma2(
    unsigned long long a, unsigned long long b, unsigned long long c) {
    unsigned long long d;
    asm("fma.rn.f32x2 %0, %1, %2, %3;" : "=l"(d) : "l"(a), "l"(b), "l"(c));
    return d;
}
__device__ __forceinline__ unsigned long long pack2(float a) {
    unsigned long long d;
    asm("mov.b64 %0, {%1, %1};" : "=l"(d) : "f"(a));
    return d;
}
__device__ __forceinline__ float2 unpack2(unsigned long long v) {
    float lo, hi;
    asm("mov.b64 {%0, %1}, %2;" : "=f"(lo), "=f"(hi) : "l"(v));
    return make_float2(lo, hi);
}
__device__ __forceinline__ float pairsum(unsigned long long v) {
    float2 p = unpack2(v);
    return p.x + p.y;
}
__device__ __forceinline__ void atom_add_release(unsigned* p) {
    unsigned old;
    asm volatile("atom.release.gpu.global.add.u32 %0, [%1], 1;"
                 : "=r"(old) : "l"(p) : "memory");
}
__device__ __forceinline__ unsigned ld_acquire(const unsigned* p) {
    unsigned v;
    asm volatile("ld.acquire.gpu.global.u32 %0, [%1];" : "=r"(v) : "l"(p) : "memory");
    return v;
}

#define SBS 132

// ---------------- shared-memory overlays for the combined kernel ----------------
struct SmemLstm {
    float h_sm[16][516];   // aliased as red[16][260] after compute
    float gsm[16][16];
    float c_sm[16][4];
};
struct SmemGemm {
    float As[2][8 * SBS];
    float Bs[2][8 * SBS];
};
union SmemU { SmemLstm l; SmemGemm g; };

// ============ standalone BIG SGEMM (Wih): 128x128 tile, BK=8, TRANSB+BIAS ============
__global__ void __launch_bounds__(256) sgemm_wih(
    const float* __restrict__ A, const float* __restrict__ Bm,
    const float* __restrict__ bi1, const float* __restrict__ bi2,
    float* __restrict__ C, int M, int N, int K)
{
    __shared__ float As[2][8 * SBS];
    __shared__ float Bs[2][8 * SBS];

    const int tid = threadIdx.x;
    const int m0 = blockIdx.y * 128, n0 = blockIdx.x * 128;
    const int row0 = (tid >> 4) << 3;
    const int col0 = (tid & 15) << 3;

    const int am = tid >> 1, akq = (tid & 1) << 2;
    const float* Ap = A + (size_t)(m0 + am) * K + akq;
    const int bn = tid >> 1, bkq = (tid & 1) << 2;
    const float* Bp = Bm + (size_t)(n0 + bn) * K + bkq;

    unsigned long long acc2[8][4];
#pragma unroll
    for (int i = 0; i < 8; i++)
#pragma unroll
        for (int j = 0; j < 4; j++) acc2[i][j] = 0ULL;

    float4 av = *(const float4*)(Ap);
    float4 bv = *(const float4*)(Bp);
    {
        float* as = As[0];
        as[(akq+0)*SBS + am] = av.x; as[(akq+1)*SBS + am] = av.y;
        as[(akq+2)*SBS + am] = av.z; as[(akq+3)*SBS + am] = av.w;
        float* bs = Bs[0];
        bs[(bkq+0)*SBS + bn] = bv.x; bs[(bkq+1)*SBS + bn] = bv.y;
        bs[(bkq+2)*SBS + bn] = bv.z; bs[(bkq+3)*SBS + bn] = bv.w;
    }
    __syncthreads();

    int buf = 0;
    for (int k0 = 8; k0 <= K; k0 += 8) {
        const bool more = (k0 < K);
        if (more) {
            av = *(const float4*)(Ap + k0);
            bv = *(const float4*)(Bp + k0);
        }
        const float* as = As[buf];
        const float* bs = Bs[buf];
#pragma unroll
        for (int kk = 0; kk < 8; kk++) {
            float4 a0 = *(const float4*)(as + kk*SBS + row0);
            float4 a1 = *(const float4*)(as + kk*SBS + row0 + 4);
            ulonglong2 b01 = *(const ulonglong2*)(bs + kk*SBS + col0);
            ulonglong2 b23 = *(const ulonglong2*)(bs + kk*SBS + col0 + 4);
            float aa[8] = {a0.x,a0.y,a0.z,a0.w,a1.x,a1.y,a1.z,a1.w};
#pragma unroll
            for (int i = 0; i < 8; i++) {
                unsigned long long ad = pack2(aa[i]);
                acc2[i][0] = ffma2(ad, b01.x, acc2[i][0]);
                acc2[i][1] = ffma2(ad, b01.y, acc2[i][1]);
                acc2[i][2] = ffma2(ad, b23.x, acc2[i][2]);
                acc2[i][3] = ffma2(ad, b23.y, acc2[i][3]);
            }
        }
        if (more) {
            float* asn = As[buf ^ 1];
            asn[(akq+0)*SBS + am] = av.x; asn[(akq+1)*SBS + am] = av.y;
            asn[(akq+2)*SBS + am] = av.z; asn[(akq+3)*SBS + am] = av.w;
            float* bsn = Bs[buf ^ 1];
            bsn[(bkq+0)*SBS + bn] = bv.x; bsn[(bkq+1)*SBS + bn] = bv.y;
            bsn[(bkq+2)*SBS + bn] = bv.z; bsn[(bkq+3)*SBS + bn] = bv.w;
        }
        __syncthreads();
        buf ^= 1;
    }

    float bias[8];
#pragma unroll
    for (int j = 0; j < 8; j++) bias[j] = bi1[n0+col0+j] + bi2[n0+col0+j];
#pragma unroll
    for (int i = 0; i < 8; i++) {
        float2 p0 = unpack2(acc2[i][0]);
        float2 p1 = unpack2(acc2[i][1]);
        float2 p2 = unpack2(acc2[i][2]);
        float2 p3 = unpack2(acc2[i][3]);
        float4 o0 = {p0.x+bias[0], p0.y+bias[1], p1.x+bias[2], p1.y+bias[3]};
        float4 o1 = {p2.x+bias[4], p2.y+bias[5], p3.x+bias[6], p3.y+bias[7]};
        float* cp = C + (size_t)(m0 + row0 + i) * N + n0 + col0;
        *(float4*)(cp)     = o0;
        *(float4*)(cp + 4) = o1;
    }
}

// ---------------- feats gemm body (no-trans, no-bias): C=A@B, M=2048 N=512 K=512 ----------------
__device__ void feats_gemm_body(SmemGemm& S, int bx, int by,
                                const float* __restrict__ A,
                                const float* __restrict__ Bm,
                                float* __restrict__ C)
{
    const int tid = threadIdx.x;
    const int m0 = by * 128, n0 = bx * 128;
    const int N = HH, K = DD;
    const int row0 = (tid >> 4) << 3;
    const int col0 = (tid & 15) << 3;

    const int am = tid >> 1, akq = (tid & 1) << 2;
    const float* Ap = A + (size_t)(m0 + am) * K + akq;
    const int bkr = tid >> 5, bn4 = (tid & 31) << 2;
    const float* Bp = Bm + (size_t)bkr * N + n0 + bn4;

    unsigned long long acc2[8][4];
#pragma unroll
    for (int i = 0; i < 8; i++)
#pragma unroll
        for (int j = 0; j < 4; j++) acc2[i][j] = 0ULL;

    float4 av = *(const float4*)(Ap);
    float4 bv = *(const float4*)(Bp);
    {
        float* as = S.As[0];
        as[(akq+0)*SBS + am] = av.x; as[(akq+1)*SBS + am] = av.y;
        as[(akq+2)*SBS + am] = av.z; as[(akq+3)*SBS + am] = av.w;
        *(float4*)(S.Bs[0] + bkr*SBS + bn4) = bv;
    }
    __syncthreads();

    int buf = 0;
    for (int k0 = 8; k0 <= K; k0 += 8) {
        const bool more = (k0 < K);
        if (more) {
            av = *(const float4*)(Ap + k0);
            bv = *(const float4*)(Bm + (size_t)(k0 + bkr) * N + n0 + bn4);
        }
        const float* as = S.As[buf];
        const float* bs = S.Bs[buf];
#pragma unroll
        for (int kk = 0; kk < 8; kk++) {
            float4 a0 = *(const float4*)(as + kk*SBS + row0);
            float4 a1 = *(const float4*)(as + kk*SBS + row0 + 4);
            ulonglong2 b01 = *(const ulonglong2*)(bs + kk*SBS + col0);
            ulonglong2 b23 = *(const ulonglong2*)(bs + kk*SBS + col0 + 4);
            float aa[8] = {a0.x,a0.y,a0.z,a0.w,a1.x,a1.y,a1.z,a1.w};
#pragma unroll
            for (int i = 0; i < 8; i++) {
                unsigned long long ad = pack2(aa[i]);
                acc2[i][0] = ffma2(ad, b01.x, acc2[i][0]);
                acc2[i][1] = ffma2(ad, b01.y, acc2[i][1]);
                acc2[i][2] = ffma2(ad, b23.x, acc2[i][2]);
                acc2[i][3] = ffma2(ad, b23.y, acc2[i][3]);
            }
        }
        if (more) {
            float* asn = S.As[buf ^ 1];
            asn[(akq+0)*SBS + am] = av.x; asn[(akq+1)*SBS + am] = av.y;
            asn[(akq+2)*SBS + am] = av.z; asn[(akq+3)*SBS + am] = av.w;
            *(float4*)(S.Bs[buf ^ 1] + bkr*SBS + bn4) = bv;
        }
        __syncthreads();
        buf ^= 1;
    }

#pragma unroll
    for (int i = 0; i < 8; i++) {
        float2 p0 = unpack2(acc2[i][0]);
        float2 p1 = unpack2(acc2[i][1]);
        float2 p2 = unpack2(acc2[i][2]);
        float2 p3 = unpack2(acc2[i][3]);
        float4 o0 = {p0.x, p0.y, p1.x, p1.y};
        float4 o1 = {p2.x, p2.y, p3.x, p3.y};
        float* cp = C + (size_t)(m0 + row0 + i) * N + n0 + col0;
        *(float4*)(cp)     = o0;
        *(float4*)(cp + 4) = o1;
    }
}

// ---------------- lstm body (128 CTAs, split release/acquire barrier) ----------------
__device__ void lstm_body(SmemLstm& S, int cta,
                          const float* __restrict__ Whh,
                          const float* __restrict__ init_c)
{
    float* red = &S.h_sm[0][0];            // [16 kc][260] scratch (aliased)

    const int tid = threadIdx.x;
    const int hd0 = cta * 4;
    const int kc = tid & 15;
    const int rr = (tid >> 4) & 3;
    const int bq = tid >> 6;

    const float* wp0 = Whh + ((size_t)(0*HH + hd0 + rr)) * HH + kc * 4;
    const float* wp1 = Whh + ((size_t)(1*HH + hd0 + rr)) * HH + kc * 4;
    const float* wp2 = Whh + ((size_t)(2*HH + hd0 + rr)) * HH + kc * 4;
    const float* wp3 = Whh + ((size_t)(3*HH + hd0 + rr)) * HH + kc * 4;

    if (tid < 64) { int b = tid >> 2, l = tid & 3; S.c_sm[b][l] = init_c[hd0 + l]; }

    const int rowX = tid >> 4;
    const int bX   = tid & 15;

    for (int s = 0; s < TT; s++) {
        float xv = __ldcg(&g_X[((size_t)s * BB + bX) * (4 * HH) + (rowX >> 2) * HH + hd0 + (rowX & 3)]);

        if (s > 0) {
            if (tid < 8) {
                while (ld_acquire(&g_cnt8[s - 1][tid * 64]) < 16u) { }
            }
        }
        __syncthreads();

        const float4* hb = (const float4*)g_hbuf[s & 1];
#pragma unroll
        for (int i2 = 0; i2 < 8; i2++) {
            int i = tid + 256 * i2;
            float4 hv = __ldcg(hb + i);
            int b = i >> 7, k4 = (i & 127) << 2;
            *(float4*)(&S.h_sm[b][k4]) = hv;
        }
        __syncthreads();

        unsigned long long acc[4][4];
#pragma unroll
        for (int g = 0; g < 4; g++)
#pragma unroll
            for (int bi = 0; bi < 4; bi++) acc[g][bi] = 0ULL;

#pragma unroll
        for (int j = 0; j < 8; j++) {
            const ulonglong2 w0 = *(const ulonglong2*)(wp0 + j * 64);
            const ulonglong2 w1 = *(const ulonglong2*)(wp1 + j * 64);
            const ulonglong2 w2 = *(const ulonglong2*)(wp2 + j * 64);
            const ulonglong2 w3 = *(const ulonglong2*)(wp3 + j * 64);
#pragma unroll
            for (int bi = 0; bi < 4; bi++) {
                const ulonglong2 h2 = *(const ulonglong2*)(&S.h_sm[bq * 4 + bi][kc * 4 + j * 64]);
                acc[0][bi] = ffma2(w0.x, h2.x, acc[0][bi]);
                acc[0][bi] = ffma2(w0.y, h2.y, acc[0][bi]);
                acc[1][bi] = ffma2(w1.x, h2.x, acc[1][bi]);
                acc[1][bi] = ffma2(w1.y, h2.y, acc[1][bi]);
                acc[2][bi] = ffma2(w2.x, h2.x, acc[2][bi]);
                acc[2][bi] = ffma2(w2.y, h2.y, acc[2][bi]);
                acc[3][bi] = ffma2(w3.x, h2.x, acc[3][bi]);
                acc[3][bi] = ffma2(w3.y, h2.y, acc[3][bi]);
            }
        }
        __syncthreads();

#pragma unroll
        for (int g = 0; g < 4; g++)
#pragma unroll
            for (int bi = 0; bi < 4; bi++)
                red[kc * 260 + (g * 4 + rr) * 16 + (bq * 4 + bi)] = pairsum(acc[g][bi]);
        __syncthreads();

        {
            float sum = xv;
#pragma unroll
            for (int i = 0; i < 16; i++) sum += red[i * 260 + rowX * 16 + bX];
            S.gsm[rowX][bX] = sum;
        }
        __syncthreads();

        if (tid < 64) {
            int b = tid >> 2, l = tid & 3;
            float gi = S.gsm[0 + l][b], gf = S.gsm[4 + l][b];
            float gg = S.gsm[8 + l][b], go = S.gsm[12 + l][b];
            float c = sigm(gf) * S.c_sm[b][l] + sigm(gi) * fast_tanh(gg);
            float h = sigm(go) * fast_tanh(c);
            S.c_sm[b][l] = c;
            g_hbuf[(s + 1) & 1][b * HH + hd0 + l] = h;
            g_qa[((size_t)b * TT + s) * HH + hd0 + l] = h;
        }
        __syncthreads();
        if (tid == 0 && s < TT - 1) {
            atom_add_release(&g_cnt8[s][(cta & 7) * 64]);
        }
    }
}

// ---------------- combined: lstm (blocks 0-127) + feats gemm (blocks 128-255) ----------------
__global__ void __launch_bounds__(256, 2) lstm_feats_kernel(
    const float* __restrict__ Whh, const float* __restrict__ init_c,
    const float* __restrict__ attn_mem,
    const float* __restrict__ attn_wm, const float* __restrict__ hop_wm,
    float* __restrict__ afeat, float* __restrict__ hfeat)
{
    __shared__ SmemU smem;
    const int bid = blockIdx.x;
    if (bid < NB_LSTM) {
        lstm_body(smem.l, bid, Whh, init_c);
    } else {
        const int lin = bid - NB_LSTM;        // 0..127
        const int bz = lin >> 6;              // 0: attn, 1: hop
        const int rem = lin & 63;
        const int bx = rem & 3;               // 4 n-tiles (512/128)
        const int by = rem >> 2;              // 16 m-tiles (2048/128)
        feats_gemm_body(smem.g, bx, by, attn_mem,
                        bz ? hop_wm : attn_wm,
                        bz ? hfeat : afeat);
    }
}

// ============ q-GEMM split-K: 64x64 tile, K-half per z, 256 threads ============
// C_z[M,N] = A[M, z*256:(z+1)*256] @ B[z*256:(z+1)*256, N];  M=1024, N=K=512
__global__ void __launch_bounds__(256) sgemm_qsplit(
    const float* __restrict__ A, const float* __restrict__ Bm,
    float* __restrict__ C0, float* __restrict__ C1)
{
    __shared__ float As[16][68];
    __shared__ float Bs[16][68];
    const int tid = threadIdx.x;
    const int N = HH, K = HH;
    const int m0 = blockIdx.y * 64, n0 = blockIdx.x * 64;
    const int kbase = blockIdx.z * 256;
    float* __restrict__ C = blockIdx.z ? C1 : C0;
    const int tx = (tid & 15) << 2, ty = (tid >> 4) << 2;
    const int lr = tid >> 2, lk = (tid & 3) << 2;
    const int bkr = tid >> 4, bnc = (tid & 15) << 2;
    float acc[4][4] = {};

    for (int k0 = kbase; k0 < kbase + 256; k0 += 16) {
        float4 av = *(const float4*)(A + (size_t)(m0 + lr) * K + k0 + lk);
        As[lk+0][lr] = av.x; As[lk+1][lr] = av.y; As[lk+2][lr] = av.z; As[lk+3][lr] = av.w;
        float4 bv = *(const float4*)(Bm + (size_t)(k0 + bkr) * N + n0 + bnc);
        *(float4*)(&Bs[bkr][bnc]) = bv;
        __syncthreads();
#pragma unroll
        for (int kk = 0; kk < 16; kk++) {
            float4 a = *(const float4*)(&As[kk][ty]);
            float4 b = *(const float4*)(&Bs[kk][tx]);
            acc[0][0] += a.x*b.x; acc[0][1] += a.x*b.y; acc[0][2] += a.x*b.z; acc[0][3] += a.x*b.w;
            acc[1][0] += a.y*b.x; acc[1][1] += a.y*b.y; acc[1][2] += a.y*b.z; acc[1][3] += a.y*b.w;
            acc[2][0] += a.z*b.x; acc[2][1] += a.z*b.y; acc[2][2] += a.z*b.z; acc[2][3] += a.z*b.w;
            acc[3][0] += a.w*b.x; acc[3][1] += a.w*b.y; acc[3][2] += a.w*b.z; acc[3][3] += a.w*b.w;
        }
        __syncthreads();
    }
#pragma unroll
    for (int i = 0; i < 4; i++) {
        float4 o = {acc[i][0], acc[i][1], acc[i][2], acc[i][3]};
        *(float4*)(C + (size_t)(m0+ty+i) * N + n0 + tx) = o;
    }
}

// ---------------- prep: xcat + maxpool + h0 + counter reset ----------------
__global__ void prep_kernel(const float* __restrict__ attn_mem,
                            const float* __restrict__ lstm_in,
                            const float* __restrict__ init_h,
                            const int* __restrict__ msz)
{
    const int t = blockIdx.x, b = blockIdx.y, d = threadIdx.x;
    if (b == 0) g_cnt8[t][d] = 0u;
    if (t == 0) {
        const int ms = msz[b];
        float m = -3.0e38f;
        for (int n = 0; n < ms; n++)
            m = fmaxf(m, attn_mem[((size_t)b * NSS + n) * DD + d]);
        g_xcat[(size_t)b * DD + d] = m;
        g_hbuf[0][b * HH + d] = init_h[d];
    } else {
        g_xcat[((size_t)t * BB + b) * DD + d] =
            lstm_in[((size_t)b * (TT - 1) + (t - 1)) * DD + d];
    }
}

// ---------------- hop: 8 t per block; split-K merge + score+softmax+weighted-sum ----------------
__global__ void __launch_bounds__(256) hop_kernel(
    const float* __restrict__ qw, const float* __restrict__ qw2,
    const float* __restrict__ feat, const float* __restrict__ v,
    const int* __restrict__ msz, float* __restrict__ qout)
{
    __shared__ float qsm[8 * HH];
    __shared__ float vsm[HH];
    __shared__ float p[8][NSS];
    __shared__ float4 part[8][HH / 4];

    const int tg = blockIdx.x, b = blockIdx.y, tid = threadIdx.x;
    const int t0 = tg * 8;
    const size_t qoff = ((size_t)b * TT + t0) * HH;
    {
        const float4* qsrc  = (const float4*)(qw  + qoff);
        const float4* qsrc2 = (const float4*)(qw2 + qoff);
        float4* qdst = (float4*)qsm;
#pragma unroll
        for (int i = 0; i < 4; i++) {
            float4 a = qsrc[tid + 256 * i];
            float4 c = qsrc2[tid + 256 * i];
            float4 o = {a.x + c.x, a.y + c.y, a.z + c.z, a.w + c.w};
            qdst[tid + 256 * i] = o;
        }
        vsm[tid] = v[tid]; vsm[tid + 256] = v[tid + 256];
    }
    __syncthreads();

    const int wid = tid >> 5, lane = tid & 31;
    const int ms = msz[b];
    const float* qt = qsm + wid * HH;
    for (int n = 0; n < NSS; n++) {
        const float* f = feat + ((size_t)b * NSS + n) * HH;
        float s = 0.f;
#pragma unroll 4
        for (int j = 0; j < 16; j++) {
            int k = lane + (j << 5);
            s += vsm[k] * fast_tanh(f[k] + qt[k]);
        }
#pragma unroll
        for (int o = 16; o; o >>= 1) s += __shfl_xor_sync(0xffffffffu, s, o);
        if (lane == 0) p[wid][n] = (n < ms) ? s : -1e30f;
    }
    __syncthreads();
    {
        float x0 = p[wid][lane], x1 = p[wid][lane+32], x2 = p[wid][lane+64], x3 = p[wid][lane+96];
        float m = fmaxf(fmaxf(x0, x1), fmaxf(x2, x3));
#pragma unroll
        for (int o = 16; o; o >>= 1) m = fmaxf(m, __shfl_xor_sync(0xffffffffu, m, o));
        float e0 = __expf(x0 - m), e1 = __expf(x1 - m), e2 = __expf(x2 - m), e3 = __expf(x3 - m);
        float s = e0 + e1 + e2 + e3;
#pragma unroll
        for (int o = 16; o; o >>= 1) s += __shfl_xor_sync(0xffffffffu, s, o);
        float inv = 1.f / s;
        p[wid][lane] = e0*inv; p[wid][lane+32] = e1*inv; p[wid][lane+64] = e2*inv; p[wid][lane+96] = e3*inv;
    }
    __syncthreads();
    {
        const int g = tid >> 7;
        const int hc = tid & 127;
        float4 acc[8] = {};
        const int nlo = g * 64;
#pragma unroll 2
        for (int n = nlo; n < nlo + 64; n++) {
            float4 fv = *(const float4*)(feat + ((size_t)b * NSS + n) * HH + hc * 4);
#pragma unroll
            for (int t = 0; t < 8; t++) {
                float pw = p[t][n];
                acc[t].x = fmaf(pw, fv.x, acc[t].x);
                acc[t].y = fmaf(pw, fv.y, acc[t].y);
                acc[t].z = fmaf(pw, fv.z, acc[t].z);
                acc[t].w = fmaf(pw, fv.w, acc[t].w);
            }
        }
        if (g == 1) {
#pragma unroll
            for (int t = 0; t < 8; t++) part[t][hc] = acc[t];
        }
        __syncthreads();
        if (g == 0) {
#pragma unroll
            for (int t = 0; t < 8; t++) {
                float4 pv = part[t][hc];
                float4 o = {acc[t].x + pv.x, acc[t].y + pv.y, acc[t].z + pv.z, acc[t].w + pv.w};
                *(float4*)(qout + ((size_t)b * TT + t0 + t) * HH + hc * 4) = o;
            }
        }
    }
}

// ---------------- final score (unmasked), split-K merge ----------------
__global__ void __launch_bounds__(256) final_kernel(
    const float* __restrict__ qw, const float* __restrict__ qw2,
    const float* __restrict__ feat, const float* __restrict__ v,
    float* __restrict__ out)
{
    __shared__ float qsm[HH];
    __shared__ float vsm[HH];
    const int t = blockIdx.x, b = blockIdx.y, tid = threadIdx.x;
    const size_t qoff = ((size_t)b * TT + t) * HH;
    qsm[tid]       = qw[qoff + tid]       + qw2[qoff + tid];
    qsm[tid + 256] = qw[qoff + tid + 256] + qw2[qoff + tid + 256];
    vsm[tid] = v[tid];    vsm[tid + 256] = v[tid + 256];
    __syncthreads();
    const int wid = tid >> 5, lane = tid & 31;
    for (int n = wid; n < NSS; n += 8) {
        const float* f = feat + ((size_t)b * NSS + n) * HH;
        float s = 0.f;
#pragma unroll 4
        for (int j = 0; j < 16; j++) {
            int k = lane + (j << 5);
            s += vsm[k] * fast_tanh(f[k] + qsm[k]);
        }
#pragma unroll
        for (int o = 16; o; o >>= 1) s += __shfl_xor_sync(0xffffffffu, s, o);
        if (lane == 0) out[(((size_t)b * TT) + t) * NSS + n] = s;
    }
}

extern "C" void kernel_launch(void* const* d_in, const int* in_sizes, int n_in,
                              void* d_out, int out_size)
{
    const float* attn_mem = (const float*)d_in[0];
    const float* lstm_in  = (const float*)d_in[1];
    const float* init_h   = (const float*)d_in[2];
    const float* init_c   = (const float*)d_in[3];
    const float* Wih      = (const float*)d_in[4];
    const float* Whh      = (const float*)d_in[5];
    const float* bih      = (const float*)d_in[6];
    const float* bhh      = (const float*)d_in[7];
    const float* attn_wm  = (const float*)d_in[8];
    const float* attn_wq  = (const float*)d_in[9];
    const float* attn_v   = (const float*)d_in[10];
    const float* hop_wm   = (const float*)d_in[11];
    const float* hop_wq   = (const float*)d_in[12];
    const float* hop_v    = (const float*)d_in[13];
    const int*   msz      = (const int*)d_in[14];
    float* out = (float*)d_out;

    float *afeat, *hfeat, *xcat, *X, *qa, *qb, *qwb, *qwb2;
    cudaGetSymbolAddress((void**)&afeat, g_attn_feat);
    cudaGetSymbolAddress((void**)&hfeat, g_hop_feat);
    cudaGetSymbolAddress((void**)&xcat,  g_xcat);
    cudaGetSymbolAddress((void**)&X,     g_X);
    cudaGetSymbolAddress((void**)&qa,    g_qa);
    cudaGetSymbolAddress((void**)&qb,    g_qb);
    cudaGetSymbolAddress((void**)&qwb,   g_qw);
    cudaGetSymbolAddress((void**)&qwb2,  g_qw2);

    prep_kernel<<<dim3(TT, BB), DD>>>(attn_mem, lstm_in, init_h, msz);
    sgemm_wih<<<dim3(16, 8), 256>>>(xcat, Wih, bih, bhh, X, TT*BB, 4*HH, DD);
    lstm_feats_kernel<<<NB_LSTM + 128, 256>>>(Whh, init_c, attn_mem,
                                              attn_wm, hop_wm, afeat, hfeat);
    // hop 1
    sgemm_qsplit<<<dim3(8, 16, 2), 256>>>(qa, hop_wq, qwb, qwb2);
    hop_kernel<<<dim3(8, BB), 256>>>(qwb, qwb2, hfeat, hop_v, msz, qb);
    // hop 2
    sgemm_qsplit<<<dim3(8, 16, 2), 256>>>(qb, hop_wq, qwb, qwb2);
    hop_kernel<<<dim3(8, BB), 256>>>(qwb, qwb2, hfeat, hop_v, msz, qa);
    // final
    sgemm_qsplit<<<dim3(8, 16, 2), 256>>>(qa, attn_wq, qwb, qwb2);
    final_kernel<<<dim3(TT, BB), 256>>>(qwb, qwb2, afeat, attn_v, out);
}